// round 7
// baseline (speedup 1.0000x reference)
#include <cuda_runtime.h>
#include <cuda_bf16.h>
#include <cstdint>
#include <math.h>

#define BATCH 128
#define EMB   256
#define NTOK  394
#define NP    196
#define M_PE  (BATCH*NP)
#define M_TOK (BATCH*NTOK)
#define SLD   400
#define NT_PAD 448
#define CAST  72                    // smem row stride in bf16 for K-chunk 64
#define TILE64 (128*CAST*2)         // 18432 B per operand per stage
#define GSMEM (3*2*TILE64)          // 110592 B dynamic smem

// ---------------- scratch ([hi|lo] split storage) ----------------
__device__ __nv_bfloat16 g_A1[(size_t)M_PE*1536];
__device__ __nv_bfloat16 g_A2[(size_t)M_PE*384];
__device__ __nv_bfloat16 g_W1T[256*1536];
__device__ __nv_bfloat16 g_W2T[256*384];
__device__ __nv_bfloat16 g_WqkvT[768*512];
__device__ __nv_bfloat16 g_WpT[256*512];
__device__ float g_bqkv[768];
__device__ float g_E1[(size_t)M_PE*EMB];
__device__ float g_E2[(size_t)M_PE*EMB];
__device__ float g_Z [(size_t)M_TOK*EMB];
__device__ __nv_bfloat16 g_Hs[(size_t)M_TOK*512];
__device__ float g_QKV[(size_t)M_TOK*768];
__device__ __nv_bfloat16 g_Qs[(size_t)256*NTOK*256];
__device__ __nv_bfloat16 g_Ks[(size_t)256*NTOK*256];
__device__ __nv_bfloat16 g_Vt[(size_t)256*128*896];
__device__ float g_S [(size_t)256*NTOK*SLD];
__device__ __nv_bfloat16 g_Ps[(size_t)256*NTOK*896];
__device__ __nv_bfloat16 g_Os[(size_t)M_TOK*512];
__device__ float g_P [(size_t)M_TOK*EMB];
__device__ float g_Z2[(size_t)M_TOK*EMB];

__device__ __forceinline__ uint32_t smem_u32(const void* p) {
    uint32_t a;
    asm("{ .reg .u64 t; cvta.to.shared.u64 t, %1; cvt.u32.u64 %0, t; }" : "=r"(a) : "l"(p));
    return a;
}
__device__ __forceinline__ void ldm4(uint32_t* r, uint32_t addr) {
    asm volatile("ldmatrix.sync.aligned.m8n8.x4.shared.b16 {%0,%1,%2,%3}, [%4];"
        : "=r"(r[0]), "=r"(r[1]), "=r"(r[2]), "=r"(r[3]) : "r"(addr));
}
__device__ __forceinline__ void mma16816(float* c, const uint32_t* a, uint32_t b0, uint32_t b1) {
    asm volatile(
        "mma.sync.aligned.m16n8k16.row.col.f32.bf16.bf16.f32 "
        "{%0,%1,%2,%3}, {%4,%5,%6,%7}, {%8,%9}, {%0,%1,%2,%3};"
        : "+f"(c[0]), "+f"(c[1]), "+f"(c[2]), "+f"(c[3])
        : "r"(a[0]), "r"(a[1]), "r"(a[2]), "r"(a[3]), "r"(b0), "r"(b1));
}
__device__ __forceinline__ void cp16(uint32_t dst, const void* src, bool pred) {
    int sz = pred ? 16 : 0;
    asm volatile("cp.async.cg.shared.global [%0], [%1], 16, %2;"
        :: "r"(dst), "l"(src), "r"(sz));
}
#define CP_COMMIT() asm volatile("cp.async.commit_group;" ::: "memory")
#define CP_WAIT0()  asm volatile("cp.async.wait_group 0;" ::: "memory")
#define CP_WAIT1()  asm volatile("cp.async.wait_group 1;" ::: "memory")

__device__ __forceinline__ void split2(float v, __nv_bfloat16& hi, __nv_bfloat16& lo) {
    hi = __float2bfloat16(v);
    lo = __float2bfloat16(v - __bfloat162float(hi));
}

// ============ warp-MMA GEMM, K-chunk 64, 3-stage cp.async + wrap addressing ============
// C[M,N] = A[M,Kv] @ B[N,Kv]^T; virtual k-offset >= wrap reads offset-wrap.
// outMode 0: fp32 C (+bias). outMode 1: split bf16 C (hi at col c, lo at col 256+c).
__global__ void __launch_bounds__(256) gemm_mma(
    const __nv_bfloat16* __restrict__ Ag, const __nv_bfloat16* __restrict__ Bg,
    const float* __restrict__ bias, void* __restrict__ Cg,
    int M, int N, int K, int lda, int ldb, int ldc, int awrap, int bwrap, int outMode,
    long sAz2, long sAz1, long sBz2, long sBz1, long sCz2, long sCz1)
{
    extern __shared__ char sm[];
    uint32_t sbase = smem_u32(sm);

    int tid = threadIdx.x, wid = tid >> 5, lane = tid & 31;
    int z = blockIdx.z;
    const __nv_bfloat16* A = Ag + (long)(z >> 1) * sAz2 + (long)(z & 1) * sAz1;
    const __nv_bfloat16* B = Bg + (long)(z >> 1) * sBz2 + (long)(z & 1) * sBz1;
    int row0 = blockIdx.y * 128, col0 = blockIdx.x * 128;
    A += (size_t)row0 * lda;
    B += (size_t)col0 * ldb;
    int esz = (outMode == 0) ? 4 : 2;
    char* Cb = (char*)Cg + ((long)(z >> 1) * sCz2 + (long)(z & 1) * sCz1
                            + (size_t)row0 * ldc + col0) * esz;
    int Mrem = M - row0, Nrem = N - col0;

    int wm = wid & 3, wn = wid >> 2;     // warp tile 32(M) x 64(N)
    bool wact = (wm * 32 < Mrem) && (wn * 64 < Nrem);

    int ldrow = tid >> 1, half = tid & 1;
    bool aval = ldrow < Mrem, bval = ldrow < Nrem;
    const char* gaBase = reinterpret_cast<const char*>(A + (size_t)ldrow * lda) + half * 64;
    const char* gbBase = reinterpret_cast<const char*>(B + (size_t)ldrow * ldb) + half * 64;
    uint32_t dstOff = ldrow * (CAST * 2) + half * 64;

    uint32_t aoff = ((wm * 32 + (lane & 15)) * CAST + ((lane >> 4) * 8)) * 2;
    uint32_t boff = ((wn * 64 + (lane & 7) + ((lane >> 4) & 1) * 8) * CAST) * 2
                  + ((lane >> 3) & 1) * 16;

    float acc[2][8][4];
    #pragma unroll
    for (int i = 0; i < 2; i++)
        #pragma unroll
        for (int j = 0; j < 8; j++)
            #pragma unroll
            for (int t = 0; t < 4; t++) acc[i][j][t] = 0.f;

    int nchunk = K >> 6;

    // prologue: chunks 0,1 -> stages 0,1
    {
        uint32_t dA = sbase + dstOff, dB = sbase + TILE64 + dstOff;
        #pragma unroll
        for (int j = 0; j < 4; j++) {
            cp16(dA + j * 16, gaBase + j * 16, aval);
            cp16(dB + j * 16, gbBase + j * 16, bval);
        }
        CP_COMMIT();
    }
    if (nchunk > 1) {
        int ka = 64 >= awrap ? 64 - awrap : 64;
        int kb = 64 >= bwrap ? 64 - bwrap : 64;
        uint32_t dA = sbase + 2 * TILE64 + dstOff, dB = sbase + 3 * TILE64 + dstOff;
        #pragma unroll
        for (int j = 0; j < 4; j++) {
            cp16(dA + j * 16, gaBase + (size_t)ka * 2 + j * 16, aval);
            cp16(dB + j * 16, gbBase + (size_t)kb * 2 + j * 16, bval);
        }
        CP_COMMIT();
    }

    for (int i = 0; i < nchunk; i++) {
        if (i + 1 < nchunk) { CP_WAIT1(); } else { CP_WAIT0(); }
        __syncthreads();

        int st = i % 3;
        uint32_t sA = sbase + st * 2 * TILE64;
        uint32_t sB = sA + TILE64;
        if (wact) {
            #pragma unroll
            for (int kk = 0; kk < 4; kk++) {
                uint32_t a0[4], a1[4], bf[4][4];
                ldm4(a0, sA + aoff + kk * 32);
                ldm4(a1, sA + aoff + 16 * CAST * 2 + kk * 32);
                #pragma unroll
                for (int j = 0; j < 4; j++)
                    ldm4(bf[j], sB + boff + j * 16 * CAST * 2 + kk * 32);
                #pragma unroll
                for (int j = 0; j < 4; j++) {
                    mma16816(acc[0][2*j],   a0, bf[j][0], bf[j][1]);
                    mma16816(acc[0][2*j+1], a0, bf[j][2], bf[j][3]);
                    mma16816(acc[1][2*j],   a1, bf[j][0], bf[j][1]);
                    mma16816(acc[1][2*j+1], a1, bf[j][2], bf[j][3]);
                }
            }
        }
        if (i + 2 < nchunk) {
            int koff = (i + 2) * 64;
            int ka = koff >= awrap ? koff - awrap : koff;
            int kb = koff >= bwrap ? koff - bwrap : koff;
            int st2 = (i + 2) % 3;
            uint32_t dA = sbase + st2 * 2 * TILE64 + dstOff;
            uint32_t dB = dA + TILE64;
            #pragma unroll
            for (int j = 0; j < 4; j++) {
                cp16(dA + j * 16, gaBase + (size_t)ka * 2 + j * 16, aval);
                cp16(dB + j * 16, gbBase + (size_t)kb * 2 + j * 16, bval);
            }
            CP_COMMIT();
        }
    }

    if (wact) {
        int grp = lane >> 2, qd = lane & 3;
        if (outMode == 0) {
            float* C = (float*)Cb;
            #pragma unroll
            for (int mt = 0; mt < 2; mt++) {
                int r0 = wm * 32 + mt * 16 + grp;
                #pragma unroll
                for (int nt = 0; nt < 8; nt++) {
                    int c = wn * 64 + nt * 8 + qd * 2;
                    float b0v = 0.f, b1v = 0.f;
                    if (bias && c < Nrem)     b0v = bias[col0 + c];
                    if (bias && c + 1 < Nrem) b1v = bias[col0 + c + 1];
                    if (r0 < Mrem) {
                        if (c < Nrem)     C[(size_t)r0 * ldc + c]     = acc[mt][nt][0] + b0v;
                        if (c + 1 < Nrem) C[(size_t)r0 * ldc + c + 1] = acc[mt][nt][1] + b1v;
                    }
                    if (r0 + 8 < Mrem) {
                        if (c < Nrem)     C[(size_t)(r0 + 8) * ldc + c]     = acc[mt][nt][2] + b0v;
                        if (c + 1 < Nrem) C[(size_t)(r0 + 8) * ldc + c + 1] = acc[mt][nt][3] + b1v;
                    }
                }
            }
        } else {
            __nv_bfloat16* C = (__nv_bfloat16*)Cb;
            #pragma unroll
            for (int mt = 0; mt < 2; mt++) {
                int r0 = wm * 32 + mt * 16 + grp;
                #pragma unroll
                for (int nt = 0; nt < 8; nt++) {
                    int c = wn * 64 + nt * 8 + qd * 2;
                    #pragma unroll
                    for (int e = 0; e < 4; e++) {
                        int rr = r0 + (e >> 1) * 8;
                        int cc = c + (e & 1);
                        if (rr < Mrem && cc < Nrem) {
                            __nv_bfloat16 hi, lo; split2(acc[mt][nt][e], hi, lo);
                            C[(size_t)rr * ldc + cc] = hi;
                            C[(size_t)rr * ldc + 256 + cc] = lo;
                        }
                    }
                }
            }
        }
    }
}

// ================ conversion / pointwise kernels ================
__device__ __forceinline__ void convW_one(const float* W, __nv_bfloat16* out,
                                          int K, int N, int id, int nOff, int ldout) {
    int k = id / N, n = id % N;
    __nv_bfloat16 hi, lo; split2(W[(size_t)k * N + n], hi, lo);
    size_t base = (size_t)(nOff + n) * ldout;
    out[base + k] = hi; out[base + K + k] = lo;
}

__global__ void convAll_kernel(const float* __restrict__ W1, const float* __restrict__ W2,
                               const float* __restrict__ Wq, const float* __restrict__ Wk,
                               const float* __restrict__ Wv, const float* __restrict__ Wp,
                               const float* __restrict__ bq, const float* __restrict__ bk,
                               const float* __restrict__ bv) {
    int id = blockIdx.x * 256 + threadIdx.x;
    if (id < 196608) { convW_one(W1, g_W1T, 768, 256, id, 0, 1536); return; }
    id -= 196608;
    if (id < 49152)  { convW_one(W2, g_W2T, 192, 256, id, 0, 384); return; }
    id -= 49152;
    if (id < 65536)  { convW_one(Wq, g_WqkvT, 256, 256, id, 0, 512); return; }
    id -= 65536;
    if (id < 65536)  { convW_one(Wk, g_WqkvT, 256, 256, id, 256, 512); return; }
    id -= 65536;
    if (id < 65536)  { convW_one(Wv, g_WqkvT, 256, 256, id, 512, 512); return; }
    id -= 65536;
    if (id < 65536)  { convW_one(Wp, g_WpT, 256, 256, id, 0, 512); return; }
    id -= 65536;
    if (id < 768) {
        float v = (id < 256) ? bq[id] : (id < 512 ? bk[id - 256] : bv[id - 512]);
        g_bqkv[id] = v;
    }
}

__global__ void extractBoth_kernel(const float* __restrict__ x) {
    int id = blockIdx.x * 256 + threadIdx.x;
    if (id < M_PE * 768) {
        int col = id % 768, rw = id / 768;
        int b = rw / NP, pi = rw % NP;
        int ph = pi / 14, pw = pi % 14;
        int c = col % 3, s = col / 3;
        int pc = s % 16, pr = s / 16;
        float v = x[(size_t)(b * 3 + c) * 50176 + (ph * 16 + pr) * 224 + (pw * 16 + pc)];
        __nv_bfloat16 hi, lo; split2(v, hi, lo);
        size_t base = (size_t)rw * 1536;
        g_A1[base + col] = hi; g_A1[base + 768 + col] = lo;
        return;
    }
    id -= M_PE * 768;
    if (id < M_PE * 192) {
        int col = id % 192, rw = id / 192;
        int b = rw / NP, j = rw % NP;
        int q = 4 * j + 3;
        int ph = q / 28, pw = q % 28;
        int c = col % 3, s = col / 3;
        int pc = s % 8, pr = s / 8;
        float v = x[(size_t)(b * 3 + c) * 50176 + (ph * 8 + pr) * 224 + (pw * 8 + pc)];
        __nv_bfloat16 hi, lo; split2(v, hi, lo);
        size_t base = (size_t)rw * 384;
        g_A2[base + col] = hi; g_A2[base + 192 + col] = lo;
    }
}

__device__ __forceinline__ float blockReduce(float v, float* sh, bool ismax) {
    int lane = threadIdx.x & 31, w = threadIdx.x >> 5;
    int nw = blockDim.x >> 5;
    #pragma unroll
    for (int o = 16; o; o >>= 1) {
        float t = __shfl_down_sync(0xffffffffu, v, o);
        v = ismax ? fmaxf(v, t) : v + t;
    }
    if (lane == 0) sh[w] = v;
    __syncthreads();
    if (w == 0) {
        v = (lane < nw) ? sh[lane] : (ismax ? -INFINITY : 0.f);
        #pragma unroll
        for (int o = 16; o; o >>= 1) {
            float t = __shfl_down_sync(0xffffffffu, v, o);
            v = ismax ? fmaxf(v, t) : v + t;
        }
        if (lane == 0) sh[0] = v;
    }
    __syncthreads();
    float r = sh[0];
    __syncthreads();
    return r;
}

__global__ void buildZ_ln_kernel(const float* __restrict__ cls1, const float* __restrict__ cls2,
                                 const float* __restrict__ gam, const float* __restrict__ bet) {
    __shared__ float sh[8];
    int tg = blockIdx.x, e = threadIdx.x;
    int t = tg % NTOK, b = tg / NTOK;
    float v;
    if (t == 0)        v = cls2[e];
    else if (t < 197)  v = g_E2[(size_t)(b * NP + (t - 1)) * EMB + e];
    else if (t == 197) v = cls1[e];
    else               v = g_E1[(size_t)(b * NP + (t - 198)) * EMB + e];
    g_Z[(size_t)tg * EMB + e] = v;
    float m = blockReduce(v, sh, false) * (1.f / EMB);
    float d = v - m;
    float var = blockReduce(d * d, sh, false) * (1.f / EMB);
    float y = d * rsqrtf(var + 1e-5f) * gam[e] + bet[e];
    __nv_bfloat16 hi, lo; split2(y, hi, lo);
    size_t base = (size_t)tg * 512;
    g_Hs[base + e] = hi; g_Hs[base + 256 + e] = lo;
}

__global__ void convQK_kernel() {
    int id = blockIdx.x * 256 + threadIdx.x;
    if (id >= 256 * NTOK * 128) return;
    int d = id & 127;
    int rem = id >> 7;
    int t = rem % NTOK;
    int zz = rem / NTOK;
    int b = zz >> 1, h = zz & 1;
    size_t qrow = (size_t)(b * NTOK + t) * 768;
    float vq = g_QKV[qrow + h * 128 + d];
    float vk = g_QKV[qrow + 256 + h * 128 + d];
    size_t base = ((size_t)zz * NTOK + t) * 256;
    __nv_bfloat16 hi, lo;
    split2(vq, hi, lo);
    g_Qs[base + d] = hi; g_Qs[base + 128 + d] = lo;
    split2(vk, hi, lo);
    g_Ks[base + d] = hi; g_Ks[base + 128 + d] = lo;
}

__global__ void convV_kernel() {
    __shared__ float tile[32][33];
    int zz = blockIdx.z;
    int d0 = blockIdx.y * 32, t0 = blockIdx.x * 32;
    int b = zz >> 1, h = zz & 1;
    int tx = threadIdx.x, ty = threadIdx.y;
    #pragma unroll
    for (int r = ty; r < 32; r += 8) {
        int tc = t0 + r;
        float v = 0.f;
        if (tc < NTOK)
            v = g_QKV[(size_t)(b * NTOK + tc) * 768 + 512 + h * 128 + d0 + tx];
        tile[r][tx] = v;
    }
    __syncthreads();
    #pragma unroll
    for (int r = ty; r < 32; r += 8) {
        int d = d0 + r;
        size_t base = ((size_t)zz * 128 + d) * 896;
        float v = tile[tx][r];
        __nv_bfloat16 hi, lo; split2(v, hi, lo);
        int tc = t0 + tx;
        g_Vt[base + tc] = hi; g_Vt[base + 448 + tc] = lo;
    }
}

__global__ void softmax_split_kernel() {
    __shared__ float sh[8];
    int zz = blockIdx.y, q = blockIdx.x, tid = threadIdx.x;
    const float* row = g_S + ((size_t)zz * NTOK + q) * SLD;
    float mx = -INFINITY;
    for (int i = tid; i < NTOK; i += 128) mx = fmaxf(mx, row[i]);
    mx = blockReduce(mx, sh, true);
    float sum = 0.f;
    for (int i = tid; i < NTOK; i += 128) sum += expf(row[i] - mx);
    sum = blockReduce(sum, sh, false);
    float inv = 1.f / (sum * 16.f);
    __nv_bfloat16* prow = g_Ps + ((size_t)zz * NTOK + q) * 896;
    for (int i = tid; i < NT_PAD; i += 128) {
        float p = (i < NTOK) ? expf(row[i] - mx) * inv : 0.f;
        __nv_bfloat16 hi, lo; split2(p, hi, lo);
        prow[i] = hi; prow[448 + i] = lo;
    }
}

__global__ void lnres_kernel(const float* __restrict__ gam, const float* __restrict__ bet) {
    __shared__ float sh[8];
    int t = blockIdx.x, e = threadIdx.x;
    float v = g_P[(size_t)t * EMB + e];
    float m = blockReduce(v, sh, false) * (1.f / EMB);
    float d = v - m;
    float var = blockReduce(d * d, sh, false) * (1.f / EMB);
    float o = d * rsqrtf(var + 1e-5f) * gam[e] + bet[e];
    g_Z2[(size_t)t * EMB + e] = g_Z[(size_t)t * EMB + e] + o;
}

__global__ void head_kernel(const float* __restrict__ gam, const float* __restrict__ bet,
                            const float* __restrict__ Wc, const float* __restrict__ bc,
                            float* __restrict__ out) {
    __shared__ float sh[8];
    int bb = blockIdx.x, e = threadIdx.x;
    const float* p = g_Z2 + (size_t)bb * NTOK * EMB + e;
    float s = 0.f;
    for (int t = 0; t < NTOK; t++) s += p[(size_t)t * EMB];
    float pooled = s * (1.f / NTOK);
    float m = blockReduce(pooled, sh, false) * (1.f / EMB);
    float d = pooled - m;
    float var = blockReduce(d * d, sh, false) * (1.f / EMB);
    float y = d * rsqrtf(var + 1e-5f) * gam[e] + bet[e];
    float p0 = blockReduce(y * Wc[e * 2 + 0], sh, false);
    float p1 = blockReduce(y * Wc[e * 2 + 1], sh, false);
    if (e == 0) {
        float l0 = p0 + bc[0], l1 = p1 + bc[1];
        float mm = fmaxf(l0, l1);
        float lse = mm + logf(expf(l0 - mm) + expf(l1 - mm));
        out[bb * 2 + 0] = l0 - lse;
        out[bb * 2 + 1] = l1 - lse;
    }
}

// ================ launch ================
extern "C" void kernel_launch(void* const* d_in, const int* in_sizes, int n_in,
                              void* d_out, int out_size)
{
    const float* x    = (const float*)d_in[0];
    const float* W1   = (const float*)d_in[1];
    const float* b1   = (const float*)d_in[2];
    const float* cls1 = (const float*)d_in[3];
    const float* W2   = (const float*)d_in[4];
    const float* b2   = (const float*)d_in[5];
    const float* cls2 = (const float*)d_in[6];
    const float* ln1g = (const float*)d_in[7];
    const float* ln1b = (const float*)d_in[8];
    const float* Wq   = (const float*)d_in[9];
    const float* bq   = (const float*)d_in[10];
    const float* Wk   = (const float*)d_in[11];
    const float* bk   = (const float*)d_in[12];
    const float* Wv   = (const float*)d_in[13];
    const float* bv   = (const float*)d_in[14];
    const float* Wp   = (const float*)d_in[15];
    const float* bp   = (const float*)d_in[16];
    const float* ln2g = (const float*)d_in[17];
    const float* ln2b = (const float*)d_in[18];
    const float* lncg = (const float*)d_in[19];
    const float* lncb = (const float*)d_in[20];
    const float* Wc   = (const float*)d_in[21];
    const float* bc   = (const float*)d_in[22];
    float* out = (float*)d_out;

    __nv_bfloat16 *A1, *A2, *W1T, *W2T, *WqkvT, *WpT, *Hs, *Qs, *Ks, *Vt, *Ps, *Os;
    float *bqkv, *QKV, *S, *P;
    cudaGetSymbolAddress((void**)&A1, g_A1);
    cudaGetSymbolAddress((void**)&A2, g_A2);
    cudaGetSymbolAddress((void**)&W1T, g_W1T);
    cudaGetSymbolAddress((void**)&W2T, g_W2T);
    cudaGetSymbolAddress((void**)&WqkvT, g_WqkvT);
    cudaGetSymbolAddress((void**)&WpT, g_WpT);
    cudaGetSymbolAddress((void**)&bqkv, g_bqkv);
    cudaGetSymbolAddress((void**)&Hs, g_Hs);
    cudaGetSymbolAddress((void**)&QKV, g_QKV);
    cudaGetSymbolAddress((void**)&Qs, g_Qs);
    cudaGetSymbolAddress((void**)&Ks, g_Ks);
    cudaGetSymbolAddress((void**)&Vt, g_Vt);
    cudaGetSymbolAddress((void**)&S, g_S);
    cudaGetSymbolAddress((void**)&Ps, g_Ps);
    cudaGetSymbolAddress((void**)&Os, g_Os);
    cudaGetSymbolAddress((void**)&P, g_P);
    float *E1, *E2;
    cudaGetSymbolAddress((void**)&E1, g_E1);
    cudaGetSymbolAddress((void**)&E2, g_E2);

    cudaFuncSetAttribute(gemm_mma, cudaFuncAttributeMaxDynamicSharedMemorySize, GSMEM);

    // 1: weight conversions
    convAll_kernel<<<(508672 + 255)/256, 256>>>(W1, W2, Wq, Wk, Wv, Wp, bq, bk, bv);
    // 2: patch extracts
    extractBoth_kernel<<<(M_PE*960 + 255)/256, 256>>>(x);
    // 3,4: patch-embed GEMMs
    gemm_mma<<<dim3(2,196,1), 256, GSMEM>>>(A1, W1T, b1, E1,
        M_PE, 256, 2304, 1536, 1536, 256, 1536, 768, 0, 0,0,0,0,0,0);
    gemm_mma<<<dim3(2,196,1), 256, GSMEM>>>(A2, W2T, b2, E2,
        M_PE, 256, 576, 384, 384, 256, 384, 192, 0, 0,0,0,0,0,0);
    // 5: fused z-assembly + LN + split
    buildZ_ln_kernel<<<M_TOK, 256>>>(cls1, cls2, ln1g, ln1b);
    // 6: fused QKV GEMM
    gemm_mma<<<dim3(6,394,1), 256, GSMEM>>>(Hs, WqkvT, bqkv, QKV,
        M_TOK, 768, 768, 512, 512, 768, 512, 256, 0, 0,0,0,0,0,0);
    // 7,8: per-head splits
    convQK_kernel<<<(256*NTOK*128 + 255)/256, 256>>>();
    convV_kernel<<<dim3(14, 4, 256), dim3(32, 8)>>>();
    // 9: S = Q @ K^T
    gemm_mma<<<dim3(4,4,256), 256, GSMEM>>>(Qs, Ks, nullptr, S,
        NTOK, NTOK, 384, 256, 256, SLD, 256, 128, 0,
        2L*NTOK*256, (long)NTOK*256, 2L*NTOK*256, (long)NTOK*256,
        2L*NTOK*SLD, (long)NTOK*SLD);
    // 10: softmax + split
    softmax_split_kernel<<<dim3(NTOK, 256), 128>>>();
    // 11: O = P @ V^T -> split bf16 directly into Os
    gemm_mma<<<dim3(1,4,256), 256, GSMEM>>>(Ps, Vt, nullptr, Os,
        NTOK, 128, 1344, 896, 896, 512, 896, 448, 1,
        2L*NTOK*896, (long)NTOK*896, 2L*128*896, 128L*896,
        (long)NTOK*512, 128L);
    // 12: projection
    gemm_mma<<<dim3(2,394,1), 256, GSMEM>>>(Os, WpT, bp, P,
        M_TOK, 256, 768, 512, 512, 256, 512, 256, 0, 0,0,0,0,0,0);
    // 13,14: residual + head
    lnres_kernel<<<M_TOK, 256>>>(ln2g, ln2b);
    head_kernel<<<BATCH, 256>>>(lncg, lncb, Wc, bc, out);
}

// round 8
// speedup vs baseline: 1.0604x; 1.0604x over previous
#include <cuda_runtime.h>
#include <cuda_bf16.h>
#include <cstdint>
#include <math.h>

#define BATCH 128
#define EMB   256
#define NTOK  394
#define NP    196
#define M_PE  (BATCH*NP)
#define M_TOK (BATCH*NTOK)
#define SLD   400
#define NT_PAD 448
#define AST   40
#define TILEB (128*AST*2)           // 10240 B per operand per stage
#define NSTG  4
#define GSMEM (NSTG*2*TILEB)        // 81920 B dynamic smem

// ---------------- scratch ([hi|lo] split storage) ----------------
__device__ __nv_bfloat16 g_A1[(size_t)M_PE*1536];
__device__ __nv_bfloat16 g_A2[(size_t)M_PE*384];
__device__ __nv_bfloat16 g_W1T[256*1536];
__device__ __nv_bfloat16 g_W2T[256*384];
__device__ __nv_bfloat16 g_WqkvT[768*512];
__device__ __nv_bfloat16 g_WpT[256*512];
__device__ float g_bqkv[768];
__device__ float g_E1[(size_t)M_PE*EMB];
__device__ float g_E2[(size_t)M_PE*EMB];
__device__ float g_Z [(size_t)M_TOK*EMB];
__device__ __nv_bfloat16 g_Hs[(size_t)M_TOK*512];
__device__ float g_QKV[(size_t)M_TOK*768];    // only V columns written
__device__ __nv_bfloat16 g_Qs[(size_t)256*NTOK*256];
__device__ __nv_bfloat16 g_Ks[(size_t)256*NTOK*256];
__device__ __nv_bfloat16 g_Vt[(size_t)256*128*896];
__device__ float g_S [(size_t)256*NTOK*SLD];
__device__ __nv_bfloat16 g_Ps[(size_t)256*NTOK*896];
__device__ __nv_bfloat16 g_Os[(size_t)M_TOK*512];
__device__ float g_P [(size_t)M_TOK*EMB];
__device__ float g_Z2[(size_t)M_TOK*EMB];

__device__ __forceinline__ uint32_t smem_u32(const void* p) {
    uint32_t a;
    asm("{ .reg .u64 t; cvta.to.shared.u64 t, %1; cvt.u32.u64 %0, t; }" : "=r"(a) : "l"(p));
    return a;
}
__device__ __forceinline__ void ldm4(uint32_t* r, uint32_t addr) {
    asm volatile("ldmatrix.sync.aligned.m8n8.x4.shared.b16 {%0,%1,%2,%3}, [%4];"
        : "=r"(r[0]), "=r"(r[1]), "=r"(r[2]), "=r"(r[3]) : "r"(addr));
}
__device__ __forceinline__ void mma16816(float* c, const uint32_t* a, uint32_t b0, uint32_t b1) {
    asm volatile(
        "mma.sync.aligned.m16n8k16.row.col.f32.bf16.bf16.f32 "
        "{%0,%1,%2,%3}, {%4,%5,%6,%7}, {%8,%9}, {%0,%1,%2,%3};"
        : "+f"(c[0]), "+f"(c[1]), "+f"(c[2]), "+f"(c[3])
        : "r"(a[0]), "r"(a[1]), "r"(a[2]), "r"(a[3]), "r"(b0), "r"(b1));
}
__device__ __forceinline__ void cp16(uint32_t dst, const void* src, bool pred) {
    int sz = pred ? 16 : 0;
    asm volatile("cp.async.cg.shared.global [%0], [%1], 16, %2;"
        :: "r"(dst), "l"(src), "r"(sz));
}
#define CP_COMMIT() asm volatile("cp.async.commit_group;" ::: "memory")
#define CP_WAIT0()  asm volatile("cp.async.wait_group 0;" ::: "memory")
#define CP_WAIT1()  asm volatile("cp.async.wait_group 1;" ::: "memory")
#define CP_WAIT2()  asm volatile("cp.async.wait_group 2;" ::: "memory")

__device__ __forceinline__ void split2(float v, __nv_bfloat16& hi, __nv_bfloat16& lo) {
    hi = __float2bfloat16(v);
    lo = __float2bfloat16(v - __bfloat162float(hi));
}

// ============ warp-MMA GEMM, K-chunk 32, 4-stage cp.async + wrap addressing ============
// C[M,N] = A[M,Kv] @ B[N,Kv]^T; virtual k-offset >= wrap reads offset-wrap.
// outMode 0: fp32 C (+bias). outMode 1: split bf16 C (hi col c, lo col 256+c).
// outMode 3: fused QKV epilogue (Q/K -> per-head split in g_Qs/g_Ks; V -> fp32 Cb).
__global__ void __launch_bounds__(256) gemm_mma(
    const __nv_bfloat16* __restrict__ Ag, const __nv_bfloat16* __restrict__ Bg,
    const float* __restrict__ bias, void* __restrict__ Cg,
    int M, int N, int K, int lda, int ldb, int ldc, int awrap, int bwrap, int outMode,
    long sAz2, long sAz1, long sBz2, long sBz1, long sCz2, long sCz1)
{
    extern __shared__ char sm[];
    uint32_t sbase = smem_u32(sm);

    int tid = threadIdx.x, wid = tid >> 5, lane = tid & 31;
    int z = blockIdx.z;
    const __nv_bfloat16* A = Ag + (long)(z >> 1) * sAz2 + (long)(z & 1) * sAz1;
    const __nv_bfloat16* B = Bg + (long)(z >> 1) * sBz2 + (long)(z & 1) * sBz1;
    int row0 = blockIdx.y * 128, col0 = blockIdx.x * 128;
    A += (size_t)row0 * lda;
    B += (size_t)col0 * ldb;
    int esz = (outMode == 1) ? 2 : 4;
    char* Cb = (char*)Cg + ((long)(z >> 1) * sCz2 + (long)(z & 1) * sCz1
                            + (size_t)row0 * ldc + col0) * esz;
    int Mrem = M - row0, Nrem = N - col0;

    int wm = wid & 3, wn = wid >> 2;     // warp tile 32(M) x 64(N)
    bool wact = (wm * 32 < Mrem) && (wn * 64 < Nrem);

    int ldrow = tid >> 1, half = tid & 1;
    bool aval = ldrow < Mrem, bval = ldrow < Nrem;
    const char* gaBase = reinterpret_cast<const char*>(A + (size_t)ldrow * lda) + half * 32;
    const char* gbBase = reinterpret_cast<const char*>(B + (size_t)ldrow * ldb) + half * 32;
    uint32_t dstOff = ldrow * (AST * 2) + half * 32;

    uint32_t aoff = ((wm * 32 + (lane & 15)) * AST + ((lane >> 4) * 8)) * 2;
    uint32_t boff = ((wn * 64 + (lane & 7) + ((lane >> 4) & 1) * 8) * AST) * 2
                  + ((lane >> 3) & 1) * 16;

    float acc[2][8][4];
    #pragma unroll
    for (int i = 0; i < 2; i++)
        #pragma unroll
        for (int j = 0; j < 8; j++)
            #pragma unroll
            for (int t = 0; t < 4; t++) acc[i][j][t] = 0.f;

    int nchunk = K >> 5;   // all call sites have nchunk >= 12

    // prologue: chunks 0,1,2 -> stages 0,1,2
    #pragma unroll
    for (int p = 0; p < 3; p++) {
        int koff = p * 32;
        int ka = koff >= awrap ? koff - awrap : koff;
        int kb = koff >= bwrap ? koff - bwrap : koff;
        uint32_t dA = sbase + p * 2 * TILEB + dstOff;
        uint32_t dB = dA + TILEB;
        cp16(dA, gaBase + (size_t)ka * 2, aval);
        cp16(dA + 16, gaBase + (size_t)ka * 2 + 16, aval);
        cp16(dB, gbBase + (size_t)kb * 2, bval);
        cp16(dB + 16, gbBase + (size_t)kb * 2 + 16, bval);
        CP_COMMIT();
    }

    for (int i = 0; i < nchunk; i++) {
        if (i + 3 <= nchunk)      { CP_WAIT2(); }
        else if (i + 2 == nchunk) { CP_WAIT1(); }
        else                      { CP_WAIT0(); }
        __syncthreads();

        int st = i & 3;
        uint32_t sA = sbase + st * 2 * TILEB;
        uint32_t sB = sA + TILEB;
        if (wact) {
            #pragma unroll
            for (int kk = 0; kk < 2; kk++) {
                uint32_t a0[4], a1[4], bf[4][4];
                ldm4(a0, sA + aoff + kk * 32);
                ldm4(a1, sA + aoff + 16 * AST * 2 + kk * 32);
                #pragma unroll
                for (int j = 0; j < 4; j++)
                    ldm4(bf[j], sB + boff + j * 16 * AST * 2 + kk * 32);
                #pragma unroll
                for (int j = 0; j < 4; j++) {
                    mma16816(acc[0][2*j],   a0, bf[j][0], bf[j][1]);
                    mma16816(acc[0][2*j+1], a0, bf[j][2], bf[j][3]);
                    mma16816(acc[1][2*j],   a1, bf[j][0], bf[j][1]);
                    mma16816(acc[1][2*j+1], a1, bf[j][2], bf[j][3]);
                }
            }
        }
        if (i + 3 < nchunk) {
            int koff = (i + 3) * 32;
            int ka = koff >= awrap ? koff - awrap : koff;
            int kb = koff >= bwrap ? koff - bwrap : koff;
            int st2 = (i + 3) & 3;
            uint32_t dA = sbase + st2 * 2 * TILEB + dstOff;
            uint32_t dB = dA + TILEB;
            cp16(dA, gaBase + (size_t)ka * 2, aval);
            cp16(dA + 16, gaBase + (size_t)ka * 2 + 16, aval);
            cp16(dB, gbBase + (size_t)kb * 2, bval);
            cp16(dB + 16, gbBase + (size_t)kb * 2 + 16, bval);
            CP_COMMIT();
        }
    }

    if (!wact) return;
    int grp = lane >> 2, qd = lane & 3;

    if (outMode == 0) {
        float* C = (float*)Cb;
        #pragma unroll
        for (int mt = 0; mt < 2; mt++) {
            int r0 = wm * 32 + mt * 16 + grp;
            #pragma unroll
            for (int nt = 0; nt < 8; nt++) {
                int c = wn * 64 + nt * 8 + qd * 2;
                float b0v = 0.f, b1v = 0.f;
                if (bias && c < Nrem)     b0v = bias[col0 + c];
                if (bias && c + 1 < Nrem) b1v = bias[col0 + c + 1];
                if (r0 < Mrem) {
                    if (c < Nrem)     C[(size_t)r0 * ldc + c]     = acc[mt][nt][0] + b0v;
                    if (c + 1 < Nrem) C[(size_t)r0 * ldc + c + 1] = acc[mt][nt][1] + b1v;
                }
                if (r0 + 8 < Mrem) {
                    if (c < Nrem)     C[(size_t)(r0 + 8) * ldc + c]     = acc[mt][nt][2] + b0v;
                    if (c + 1 < Nrem) C[(size_t)(r0 + 8) * ldc + c + 1] = acc[mt][nt][3] + b1v;
                }
            }
        }
    } else if (outMode == 1) {
        __nv_bfloat16* C = (__nv_bfloat16*)Cb;
        #pragma unroll
        for (int mt = 0; mt < 2; mt++) {
            int r0 = wm * 32 + mt * 16 + grp;
            #pragma unroll
            for (int nt = 0; nt < 8; nt++) {
                int c = wn * 64 + nt * 8 + qd * 2;
                #pragma unroll
                for (int e = 0; e < 4; e++) {
                    int rr = r0 + (e >> 1) * 8;
                    int cc = c + (e & 1);
                    if (rr < Mrem && cc < Nrem) {
                        __nv_bfloat16 hi, lo; split2(acc[mt][nt][e], hi, lo);
                        C[(size_t)rr * ldc + cc] = hi;
                        C[(size_t)rr * ldc + 256 + cc] = lo;
                    }
                }
            }
        }
    } else { // outMode 3: fused QKV epilogue
        #pragma unroll
        for (int mt = 0; mt < 2; mt++) {
            int r0 = wm * 32 + mt * 16 + grp;
            #pragma unroll
            for (int nt = 0; nt < 8; nt++) {
                int c = wn * 64 + nt * 8 + qd * 2;
                #pragma unroll
                for (int e = 0; e < 4; e++) {
                    int rr = r0 + (e >> 1) * 8;
                    int cc = c + (e & 1);
                    if (rr < Mrem) {
                        int gc = col0 + cc;
                        float val = acc[mt][nt][e] + bias[gc];
                        if (gc < 512) {
                            int gm = row0 + rr;
                            int b = gm / NTOK, t = gm - b * NTOK;
                            int h = (gc >> 7) & 1;
                            int d = gc & 127;
                            size_t base = ((size_t)(b * 2 + h) * NTOK + t) * 256;
                            __nv_bfloat16 hi, lo; split2(val, hi, lo);
                            __nv_bfloat16* dst = (gc < 256) ? g_Qs : g_Ks;
                            dst[base + d] = hi; dst[base + 128 + d] = lo;
                        } else {
                            ((float*)Cb)[(size_t)rr * ldc + cc] = val;
                        }
                    }
                }
            }
        }
    }
}

// ================ conversion / pointwise kernels ================
__device__ __forceinline__ void convW_one(const float* W, __nv_bfloat16* out,
                                          int K, int N, int id, int nOff, int ldout) {
    int k = id / N, n = id % N;
    __nv_bfloat16 hi, lo; split2(W[(size_t)k * N + n], hi, lo);
    size_t base = (size_t)(nOff + n) * ldout;
    out[base + k] = hi; out[base + K + k] = lo;
}

__global__ void convAll_kernel(const float* __restrict__ W1, const float* __restrict__ W2,
                               const float* __restrict__ Wq, const float* __restrict__ Wk,
                               const float* __restrict__ Wv, const float* __restrict__ Wp,
                               const float* __restrict__ bq, const float* __restrict__ bk,
                               const float* __restrict__ bv) {
    int id = blockIdx.x * 256 + threadIdx.x;
    if (id < 196608) { convW_one(W1, g_W1T, 768, 256, id, 0, 1536); return; }
    id -= 196608;
    if (id < 49152)  { convW_one(W2, g_W2T, 192, 256, id, 0, 384); return; }
    id -= 49152;
    if (id < 65536)  { convW_one(Wq, g_WqkvT, 256, 256, id, 0, 512); return; }
    id -= 65536;
    if (id < 65536)  { convW_one(Wk, g_WqkvT, 256, 256, id, 256, 512); return; }
    id -= 65536;
    if (id < 65536)  { convW_one(Wv, g_WqkvT, 256, 256, id, 512, 512); return; }
    id -= 65536;
    if (id < 65536)  { convW_one(Wp, g_WpT, 256, 256, id, 0, 512); return; }
    id -= 65536;
    if (id < 768) {
        float v = (id < 256) ? bq[id] : (id < 512 ? bk[id - 256] : bv[id - 512]);
        g_bqkv[id] = v;
    }
}

__global__ void extractBoth_kernel(const float* __restrict__ x) {
    int id = blockIdx.x * 256 + threadIdx.x;
    if (id < M_PE * 768) {
        int col = id % 768, rw = id / 768;
        int b = rw / NP, pi = rw % NP;
        int ph = pi / 14, pw = pi % 14;
        int c = col % 3, s = col / 3;
        int pc = s % 16, pr = s / 16;
        float v = x[(size_t)(b * 3 + c) * 50176 + (ph * 16 + pr) * 224 + (pw * 16 + pc)];
        __nv_bfloat16 hi, lo; split2(v, hi, lo);
        size_t base = (size_t)rw * 1536;
        g_A1[base + col] = hi; g_A1[base + 768 + col] = lo;
        return;
    }
    id -= M_PE * 768;
    if (id < M_PE * 192) {
        int col = id % 192, rw = id / 192;
        int b = rw / NP, j = rw % NP;
        int q = 4 * j + 3;
        int ph = q / 28, pw = q % 28;
        int c = col % 3, s = col / 3;
        int pc = s % 8, pr = s / 8;
        float v = x[(size_t)(b * 3 + c) * 50176 + (ph * 8 + pr) * 224 + (pw * 8 + pc)];
        __nv_bfloat16 hi, lo; split2(v, hi, lo);
        size_t base = (size_t)rw * 384;
        g_A2[base + col] = hi; g_A2[base + 192 + col] = lo;
    }
}

__device__ __forceinline__ float blockReduce(float v, float* sh, bool ismax) {
    int lane = threadIdx.x & 31, w = threadIdx.x >> 5;
    int nw = blockDim.x >> 5;
    #pragma unroll
    for (int o = 16; o; o >>= 1) {
        float t = __shfl_down_sync(0xffffffffu, v, o);
        v = ismax ? fmaxf(v, t) : v + t;
    }
    if (lane == 0) sh[w] = v;
    __syncthreads();
    if (w == 0) {
        v = (lane < nw) ? sh[lane] : (ismax ? -INFINITY : 0.f);
        #pragma unroll
        for (int o = 16; o; o >>= 1) {
            float t = __shfl_down_sync(0xffffffffu, v, o);
            v = ismax ? fmaxf(v, t) : v + t;
        }
        if (lane == 0) sh[0] = v;
    }
    __syncthreads();
    float r = sh[0];
    __syncthreads();
    return r;
}

__global__ void buildZ_ln_kernel(const float* __restrict__ cls1, const float* __restrict__ cls2,
                                 const float* __restrict__ gam, const float* __restrict__ bet) {
    __shared__ float sh[8];
    int tg = blockIdx.x, e = threadIdx.x;
    int t = tg % NTOK, b = tg / NTOK;
    float v;
    if (t == 0)        v = cls2[e];
    else if (t < 197)  v = g_E2[(size_t)(b * NP + (t - 1)) * EMB + e];
    else if (t == 197) v = cls1[e];
    else               v = g_E1[(size_t)(b * NP + (t - 198)) * EMB + e];
    g_Z[(size_t)tg * EMB + e] = v;
    float m = blockReduce(v, sh, false) * (1.f / EMB);
    float d = v - m;
    float var = blockReduce(d * d, sh, false) * (1.f / EMB);
    float y = d * rsqrtf(var + 1e-5f) * gam[e] + bet[e];
    __nv_bfloat16 hi, lo; split2(y, hi, lo);
    size_t base = (size_t)tg * 512;
    g_Hs[base + e] = hi; g_Hs[base + 256 + e] = lo;
}

__global__ void convV_kernel() {
    __shared__ float tile[32][33];
    int zz = blockIdx.z;
    int d0 = blockIdx.y * 32, t0 = blockIdx.x * 32;
    int b = zz >> 1, h = zz & 1;
    int tx = threadIdx.x, ty = threadIdx.y;
    #pragma unroll
    for (int r = ty; r < 32; r += 8) {
        int tc = t0 + r;
        float v = 0.f;
        if (tc < NTOK)
            v = g_QKV[(size_t)(b * NTOK + tc) * 768 + 512 + h * 128 + d0 + tx];
        tile[r][tx] = v;
    }
    __syncthreads();
    #pragma unroll
    for (int r = ty; r < 32; r += 8) {
        int d = d0 + r;
        size_t base = ((size_t)zz * 128 + d) * 896;
        float v = tile[tx][r];
        __nv_bfloat16 hi, lo; split2(v, hi, lo);
        int tc = t0 + tx;
        g_Vt[base + tc] = hi; g_Vt[base + 448 + tc] = lo;
    }
}

__global__ void softmax_split_kernel() {
    __shared__ float sh[8];
    int zz = blockIdx.y, q = blockIdx.x, tid = threadIdx.x;
    const float* row = g_S + ((size_t)zz * NTOK + q) * SLD;
    float mx = -INFINITY;
    for (int i = tid; i < NTOK; i += 128) mx = fmaxf(mx, row[i]);
    mx = blockReduce(mx, sh, true);
    float sum = 0.f;
    for (int i = tid; i < NTOK; i += 128) sum += expf(row[i] - mx);
    sum = blockReduce(sum, sh, false);
    float inv = 1.f / (sum * 16.f);
    __nv_bfloat16* prow = g_Ps + ((size_t)zz * NTOK + q) * 896;
    for (int i = tid; i < NT_PAD; i += 128) {
        float p = (i < NTOK) ? expf(row[i] - mx) * inv : 0.f;
        __nv_bfloat16 hi, lo; split2(p, hi, lo);
        prow[i] = hi; prow[448 + i] = lo;
    }
}

__global__ void lnres_kernel(const float* __restrict__ gam, const float* __restrict__ bet) {
    __shared__ float sh[8];
    int t = blockIdx.x, e = threadIdx.x;
    float v = g_P[(size_t)t * EMB + e];
    float m = blockReduce(v, sh, false) * (1.f / EMB);
    float d = v - m;
    float var = blockReduce(d * d, sh, false) * (1.f / EMB);
    float o = d * rsqrtf(var + 1e-5f) * gam[e] + bet[e];
    g_Z2[(size_t)t * EMB + e] = g_Z[(size_t)t * EMB + e] + o;
}

__global__ void head_kernel(const float* __restrict__ gam, const float* __restrict__ bet,
                            const float* __restrict__ Wc, const float* __restrict__ bc,
                            float* __restrict__ out) {
    __shared__ float sh[8];
    int bb = blockIdx.x, e = threadIdx.x;
    const float* p = g_Z2 + (size_t)bb * NTOK * EMB + e;
    float s = 0.f;
    for (int t = 0; t < NTOK; t++) s += p[(size_t)t * EMB];
    float pooled = s * (1.f / NTOK);
    float m = blockReduce(pooled, sh, false) * (1.f / EMB);
    float d = pooled - m;
    float var = blockReduce(d * d, sh, false) * (1.f / EMB);
    float y = d * rsqrtf(var + 1e-5f) * gam[e] + bet[e];
    float p0 = blockReduce(y * Wc[e * 2 + 0], sh, false);
    float p1 = blockReduce(y * Wc[e * 2 + 1], sh, false);
    if (e == 0) {
        float l0 = p0 + bc[0], l1 = p1 + bc[1];
        float mm = fmaxf(l0, l1);
        float lse = mm + logf(expf(l0 - mm) + expf(l1 - mm));
        out[bb * 2 + 0] = l0 - lse;
        out[bb * 2 + 1] = l1 - lse;
    }
}

// ================ launch ================
extern "C" void kernel_launch(void* const* d_in, const int* in_sizes, int n_in,
                              void* d_out, int out_size)
{
    const float* x    = (const float*)d_in[0];
    const float* W1   = (const float*)d_in[1];
    const float* b1   = (const float*)d_in[2];
    const float* cls1 = (const float*)d_in[3];
    const float* W2   = (const float*)d_in[4];
    const float* b2   = (const float*)d_in[5];
    const float* cls2 = (const float*)d_in[6];
    const float* ln1g = (const float*)d_in[7];
    const float* ln1b = (const float*)d_in[8];
    const float* Wq   = (const float*)d_in[9];
    const float* bq   = (const float*)d_in[10];
    const float* Wk   = (const float*)d_in[11];
    const float* bk   = (const float*)d_in[12];
    const float* Wv   = (const float*)d_in[13];
    const float* bv   = (const float*)d_in[14];
    const float* Wp   = (const float*)d_in[15];
    const float* bp   = (const float*)d_in[16];
    const float* ln2g = (const float*)d_in[17];
    const float* ln2b = (const float*)d_in[18];
    const float* lncg = (const float*)d_in[19];
    const float* lncb = (const float*)d_in[20];
    const float* Wc   = (const float*)d_in[21];
    const float* bc   = (const float*)d_in[22];
    float* out = (float*)d_out;

    __nv_bfloat16 *A1, *A2, *W1T, *W2T, *WqkvT, *WpT, *Hs, *Qs, *Ks, *Vt, *Ps, *Os;
    float *bqkv, *QKV, *S, *P, *E1, *E2;
    cudaGetSymbolAddress((void**)&A1, g_A1);
    cudaGetSymbolAddress((void**)&A2, g_A2);
    cudaGetSymbolAddress((void**)&W1T, g_W1T);
    cudaGetSymbolAddress((void**)&W2T, g_W2T);
    cudaGetSymbolAddress((void**)&WqkvT, g_WqkvT);
    cudaGetSymbolAddress((void**)&WpT, g_WpT);
    cudaGetSymbolAddress((void**)&bqkv, g_bqkv);
    cudaGetSymbolAddress((void**)&Hs, g_Hs);
    cudaGetSymbolAddress((void**)&QKV, g_QKV);
    cudaGetSymbolAddress((void**)&Qs, g_Qs);
    cudaGetSymbolAddress((void**)&Ks, g_Ks);
    cudaGetSymbolAddress((void**)&Vt, g_Vt);
    cudaGetSymbolAddress((void**)&S, g_S);
    cudaGetSymbolAddress((void**)&Ps, g_Ps);
    cudaGetSymbolAddress((void**)&Os, g_Os);
    cudaGetSymbolAddress((void**)&P, g_P);
    cudaGetSymbolAddress((void**)&E1, g_E1);
    cudaGetSymbolAddress((void**)&E2, g_E2);

    cudaFuncSetAttribute(gemm_mma, cudaFuncAttributeMaxDynamicSharedMemorySize, GSMEM);

    // 1: weight conversions
    convAll_kernel<<<(508672 + 255)/256, 256>>>(W1, W2, Wq, Wk, Wv, Wp, bq, bk, bv);
    // 2: patch extracts
    extractBoth_kernel<<<(M_PE*960 + 255)/256, 256>>>(x);
    // 3,4: patch-embed GEMMs
    gemm_mma<<<dim3(2,196,1), 256, GSMEM>>>(A1, W1T, b1, E1,
        M_PE, 256, 2304, 1536, 1536, 256, 1536, 768, 0, 0,0,0,0,0,0);
    gemm_mma<<<dim3(2,196,1), 256, GSMEM>>>(A2, W2T, b2, E2,
        M_PE, 256, 576, 384, 384, 256, 384, 192, 0, 0,0,0,0,0,0);
    // 5: fused z-assembly + LN + split
    buildZ_ln_kernel<<<M_TOK, 256>>>(cls1, cls2, ln1g, ln1b);
    // 6: fused QKV GEMM with Q/K split epilogue (V -> fp32 g_QKV)
    gemm_mma<<<dim3(6,394,1), 256, GSMEM>>>(Hs, WqkvT, bqkv, QKV,
        M_TOK, 768, 768, 512, 512, 768, 512, 256, 3, 0,0,0,0,0,0);
    // 7: V transpose + split
    convV_kernel<<<dim3(14, 4, 256), dim3(32, 8)>>>();
    // 8: S = Q @ K^T
    gemm_mma<<<dim3(4,4,256), 256, GSMEM>>>(Qs, Ks, nullptr, S,
        NTOK, NTOK, 384, 256, 256, SLD, 256, 128, 0,
        2L*NTOK*256, (long)NTOK*256, 2L*NTOK*256, (long)NTOK*256,
        2L*NTOK*SLD, (long)NTOK*SLD);
    // 9: softmax + split
    softmax_split_kernel<<<dim3(NTOK, 256), 128>>>();
    // 10: O = P @ V^T -> split bf16 directly into Os
    gemm_mma<<<dim3(1,4,256), 256, GSMEM>>>(Ps, Vt, nullptr, Os,
        NTOK, 128, 1344, 896, 896, 512, 896, 448, 1,
        2L*NTOK*896, (long)NTOK*896, 2L*128*896, 128L*896,
        (long)NTOK*512, 128L);
    // 11: projection
    gemm_mma<<<dim3(2,394,1), 256, GSMEM>>>(Os, WpT, bp, P,
        M_TOK, 256, 768, 512, 512, 256, 512, 256, 0, 0,0,0,0,0,0);
    // 12,13: residual + head
    lnres_kernel<<<M_TOK, 256>>>(ln2g, ln2b);
    head_kernel<<<BATCH, 256>>>(lncg, lncb, Wc, bc, out);
}

// round 9
// speedup vs baseline: 1.1748x; 1.1079x over previous
#include <cuda_runtime.h>
#include <cuda_bf16.h>
#include <cstdint>
#include <math.h>

#define BATCH 128
#define EMB   256
#define NTOK  394
#define NP    196
#define M_PE  (BATCH*NP)
#define M_TOK (BATCH*NTOK)
#define SLD   400
#define NT_PAD 448
#define AST   40
#define TILEB (128*AST*2)           // 10240 B per operand per stage
#define NSTG  4
#define GSMEM (NSTG*2*TILEB)        // 81920 B dynamic smem

// ---------------- scratch ([hi|lo] split storage) ----------------
__device__ __nv_bfloat16 g_A1[(size_t)M_PE*1536];
__device__ __nv_bfloat16 g_A2[(size_t)M_PE*384];
__device__ __nv_bfloat16 g_W1T[256*1536];
__device__ __nv_bfloat16 g_W2T[256*384];
__device__ __nv_bfloat16 g_WqkvT[768*512];
__device__ __nv_bfloat16 g_WpT[256*512];
__device__ float g_bqkv[768];
__device__ float g_E1[(size_t)M_PE*EMB];
__device__ float g_E2[(size_t)M_PE*EMB];
__device__ float g_Z [(size_t)M_TOK*EMB];
__device__ __nv_bfloat16 g_Hs[(size_t)M_TOK*512];
__device__ __nv_bfloat16 g_Qs[(size_t)256*NTOK*256];
__device__ __nv_bfloat16 g_Ks[(size_t)256*NTOK*256];
__device__ __nv_bfloat16 g_Vt[(size_t)256*128*896];
__device__ float g_S [(size_t)256*NTOK*SLD];
__device__ __nv_bfloat16 g_Ps[(size_t)256*NTOK*896];
__device__ __nv_bfloat16 g_Os[(size_t)M_TOK*512];
__device__ float g_P [(size_t)M_TOK*EMB];
__device__ float g_pool[BATCH*EMB];

__device__ __forceinline__ uint32_t smem_u32(const void* p) {
    uint32_t a;
    asm("{ .reg .u64 t; cvta.to.shared.u64 t, %1; cvt.u32.u64 %0, t; }" : "=r"(a) : "l"(p));
    return a;
}
__device__ __forceinline__ void ldm4(uint32_t* r, uint32_t addr) {
    asm volatile("ldmatrix.sync.aligned.m8n8.x4.shared.b16 {%0,%1,%2,%3}, [%4];"
        : "=r"(r[0]), "=r"(r[1]), "=r"(r[2]), "=r"(r[3]) : "r"(addr));
}
__device__ __forceinline__ void mma16816(float* c, const uint32_t* a, uint32_t b0, uint32_t b1) {
    asm volatile(
        "mma.sync.aligned.m16n8k16.row.col.f32.bf16.bf16.f32 "
        "{%0,%1,%2,%3}, {%4,%5,%6,%7}, {%8,%9}, {%0,%1,%2,%3};"
        : "+f"(c[0]), "+f"(c[1]), "+f"(c[2]), "+f"(c[3])
        : "r"(a[0]), "r"(a[1]), "r"(a[2]), "r"(a[3]), "r"(b0), "r"(b1));
}
__device__ __forceinline__ void cp16(uint32_t dst, const void* src, bool pred) {
    int sz = pred ? 16 : 0;
    asm volatile("cp.async.cg.shared.global [%0], [%1], 16, %2;"
        :: "r"(dst), "l"(src), "r"(sz));
}
#define CP_COMMIT() asm volatile("cp.async.commit_group;" ::: "memory")
#define CP_WAIT0()  asm volatile("cp.async.wait_group 0;" ::: "memory")
#define CP_WAIT1()  asm volatile("cp.async.wait_group 1;" ::: "memory")
#define CP_WAIT2()  asm volatile("cp.async.wait_group 2;" ::: "memory")

__device__ __forceinline__ void split2(float v, __nv_bfloat16& hi, __nv_bfloat16& lo) {
    hi = __float2bfloat16(v);
    lo = __float2bfloat16(v - __bfloat162float(hi));
}

// ============ warp-MMA GEMM, K-chunk 32, 4-stage cp.async + wrap addressing ============
// outMode 0: fp32 C (+bias). outMode 1: split bf16 C (hi col c, lo col 256+c).
// outMode 3: fused QKV epilogue (Q/K -> g_Qs/g_Ks per-head split; V -> g_Vt transposed split).
__global__ void __launch_bounds__(256) gemm_mma(
    const __nv_bfloat16* __restrict__ Ag, const __nv_bfloat16* __restrict__ Bg,
    const float* __restrict__ bias, void* __restrict__ Cg,
    int M, int N, int K, int lda, int ldb, int ldc, int awrap, int bwrap, int outMode,
    long sAz2, long sAz1, long sBz2, long sBz1, long sCz2, long sCz1)
{
    extern __shared__ char sm[];
    uint32_t sbase = smem_u32(sm);

    int tid = threadIdx.x, wid = tid >> 5, lane = tid & 31;
    int z = blockIdx.z;
    const __nv_bfloat16* A = Ag + (long)(z >> 1) * sAz2 + (long)(z & 1) * sAz1;
    const __nv_bfloat16* B = Bg + (long)(z >> 1) * sBz2 + (long)(z & 1) * sBz1;
    int row0 = blockIdx.y * 128, col0 = blockIdx.x * 128;
    A += (size_t)row0 * lda;
    B += (size_t)col0 * ldb;
    int esz = (outMode == 1) ? 2 : 4;
    char* Cb = (char*)Cg + ((long)(z >> 1) * sCz2 + (long)(z & 1) * sCz1
                            + (size_t)row0 * ldc + col0) * esz;
    int Mrem = M - row0, Nrem = N - col0;

    int wm = wid & 3, wn = wid >> 2;     // warp tile 32(M) x 64(N)
    bool wact = (wm * 32 < Mrem) && (wn * 64 < Nrem);

    int ldrow = tid >> 1, half = tid & 1;
    bool aval = ldrow < Mrem, bval = ldrow < Nrem;
    const char* gaBase = reinterpret_cast<const char*>(A + (size_t)ldrow * lda) + half * 32;
    const char* gbBase = reinterpret_cast<const char*>(B + (size_t)ldrow * ldb) + half * 32;
    uint32_t dstOff = ldrow * (AST * 2) + half * 32;

    uint32_t aoff = ((wm * 32 + (lane & 15)) * AST + ((lane >> 4) * 8)) * 2;
    uint32_t boff = ((wn * 64 + (lane & 7) + ((lane >> 4) & 1) * 8) * AST) * 2
                  + ((lane >> 3) & 1) * 16;

    float acc[2][8][4];
    #pragma unroll
    for (int i = 0; i < 2; i++)
        #pragma unroll
        for (int j = 0; j < 8; j++)
            #pragma unroll
            for (int t = 0; t < 4; t++) acc[i][j][t] = 0.f;

    int nchunk = K >> 5;

    // prologue: chunks 0,1,2 -> stages 0,1,2
    #pragma unroll
    for (int p = 0; p < 3; p++) {
        int koff = p * 32;
        int ka = koff >= awrap ? koff - awrap : koff;
        int kb = koff >= bwrap ? koff - bwrap : koff;
        uint32_t dA = sbase + p * 2 * TILEB + dstOff;
        uint32_t dB = dA + TILEB;
        cp16(dA, gaBase + (size_t)ka * 2, aval);
        cp16(dA + 16, gaBase + (size_t)ka * 2 + 16, aval);
        cp16(dB, gbBase + (size_t)kb * 2, bval);
        cp16(dB + 16, gbBase + (size_t)kb * 2 + 16, bval);
        CP_COMMIT();
    }

    for (int i = 0; i < nchunk; i++) {
        if (i + 3 <= nchunk)      { CP_WAIT2(); }
        else if (i + 2 == nchunk) { CP_WAIT1(); }
        else                      { CP_WAIT0(); }
        __syncthreads();

        int st = i & 3;
        uint32_t sA = sbase + st * 2 * TILEB;
        uint32_t sB = sA + TILEB;
        if (wact) {
            #pragma unroll
            for (int kk = 0; kk < 2; kk++) {
                uint32_t a0[4], a1[4], bf[4][4];
                ldm4(a0, sA + aoff + kk * 32);
                ldm4(a1, sA + aoff + 16 * AST * 2 + kk * 32);
                #pragma unroll
                for (int j = 0; j < 4; j++)
                    ldm4(bf[j], sB + boff + j * 16 * AST * 2 + kk * 32);
                #pragma unroll
                for (int j = 0; j < 4; j++) {
                    mma16816(acc[0][2*j],   a0, bf[j][0], bf[j][1]);
                    mma16816(acc[0][2*j+1], a0, bf[j][2], bf[j][3]);
                    mma16816(acc[1][2*j],   a1, bf[j][0], bf[j][1]);
                    mma16816(acc[1][2*j+1], a1, bf[j][2], bf[j][3]);
                }
            }
        }
        if (i + 3 < nchunk) {
            int koff = (i + 3) * 32;
            int ka = koff >= awrap ? koff - awrap : koff;
            int kb = koff >= bwrap ? koff - bwrap : koff;
            int st2 = (i + 3) & 3;
            uint32_t dA = sbase + st2 * 2 * TILEB + dstOff;
            uint32_t dB = dA + TILEB;
            cp16(dA, gaBase + (size_t)ka * 2, aval);
            cp16(dA + 16, gaBase + (size_t)ka * 2 + 16, aval);
            cp16(dB, gbBase + (size_t)kb * 2, bval);
            cp16(dB + 16, gbBase + (size_t)kb * 2 + 16, bval);
            CP_COMMIT();
        }
    }

    if (!wact) return;
    int grp = lane >> 2, qd = lane & 3;

    if (outMode == 0) {
        float* C = (float*)Cb;
        #pragma unroll
        for (int mt = 0; mt < 2; mt++) {
            int r0 = wm * 32 + mt * 16 + grp;
            #pragma unroll
            for (int nt = 0; nt < 8; nt++) {
                int c = wn * 64 + nt * 8 + qd * 2;
                float b0v = 0.f, b1v = 0.f;
                if (bias && c < Nrem)     b0v = bias[col0 + c];
                if (bias && c + 1 < Nrem) b1v = bias[col0 + c + 1];
                if (r0 < Mrem) {
                    if (c < Nrem)     C[(size_t)r0 * ldc + c]     = acc[mt][nt][0] + b0v;
                    if (c + 1 < Nrem) C[(size_t)r0 * ldc + c + 1] = acc[mt][nt][1] + b1v;
                }
                if (r0 + 8 < Mrem) {
                    if (c < Nrem)     C[(size_t)(r0 + 8) * ldc + c]     = acc[mt][nt][2] + b0v;
                    if (c + 1 < Nrem) C[(size_t)(r0 + 8) * ldc + c + 1] = acc[mt][nt][3] + b1v;
                }
            }
        }
    } else if (outMode == 1) {
        __nv_bfloat16* C = (__nv_bfloat16*)Cb;
        #pragma unroll
        for (int mt = 0; mt < 2; mt++) {
            int r0 = wm * 32 + mt * 16 + grp;
            #pragma unroll
            for (int nt = 0; nt < 8; nt++) {
                int c = wn * 64 + nt * 8 + qd * 2;
                #pragma unroll
                for (int e = 0; e < 4; e++) {
                    int rr = r0 + (e >> 1) * 8;
                    int cc = c + (e & 1);
                    if (rr < Mrem && cc < Nrem) {
                        __nv_bfloat16 hi, lo; split2(acc[mt][nt][e], hi, lo);
                        C[(size_t)rr * ldc + cc] = hi;
                        C[(size_t)rr * ldc + 256 + cc] = lo;
                    }
                }
            }
        }
    } else { // outMode 3: fused QKV epilogue (Q/K split + V transposed split)
        #pragma unroll
        for (int mt = 0; mt < 2; mt++) {
            int r0 = wm * 32 + mt * 16 + grp;
            #pragma unroll
            for (int nt = 0; nt < 8; nt++) {
                int c = wn * 64 + nt * 8 + qd * 2;
                #pragma unroll
                for (int e = 0; e < 4; e++) {
                    int rr = r0 + (e >> 1) * 8;
                    int cc = c + (e & 1);
                    if (rr < Mrem) {
                        int gc = col0 + cc;
                        float val = acc[mt][nt][e] + bias[gc];
                        int gm = row0 + rr;
                        int b = gm / NTOK, t = gm - b * NTOK;
                        int h = (gc >> 7) & 1;
                        int d = gc & 127;
                        __nv_bfloat16 hi, lo; split2(val, hi, lo);
                        if (gc < 512) {
                            size_t base = ((size_t)(b * 2 + h) * NTOK + t) * 256;
                            __nv_bfloat16* dst = (gc < 256) ? g_Qs : g_Ks;
                            dst[base + d] = hi; dst[base + 128 + d] = lo;
                        } else {
                            size_t base = ((size_t)(b * 2 + h) * 128 + d) * 896 + t;
                            g_Vt[base] = hi; g_Vt[base + 448] = lo;
                        }
                    }
                }
            }
        }
    }
}

// ================ conversion / pointwise kernels ================
__device__ __forceinline__ void convW_one(const float* W, __nv_bfloat16* out,
                                          int K, int N, int id, int nOff, int ldout) {
    int k = id / N, n = id % N;
    __nv_bfloat16 hi, lo; split2(W[(size_t)k * N + n], hi, lo);
    size_t base = (size_t)(nOff + n) * ldout;
    out[base + k] = hi; out[base + K + k] = lo;
}

// weight conversions + bias concat + pool zeroing
__global__ void convAll_kernel(const float* __restrict__ W1, const float* __restrict__ W2,
                               const float* __restrict__ Wq, const float* __restrict__ Wk,
                               const float* __restrict__ Wv, const float* __restrict__ Wp,
                               const float* __restrict__ bq, const float* __restrict__ bk,
                               const float* __restrict__ bv) {
    int id = blockIdx.x * 256 + threadIdx.x;
    if (id < 196608) { convW_one(W1, g_W1T, 768, 256, id, 0, 1536); return; }
    id -= 196608;
    if (id < 49152)  { convW_one(W2, g_W2T, 192, 256, id, 0, 384); return; }
    id -= 49152;
    if (id < 65536)  { convW_one(Wq, g_WqkvT, 256, 256, id, 0, 512); return; }
    id -= 65536;
    if (id < 65536)  { convW_one(Wk, g_WqkvT, 256, 256, id, 256, 512); return; }
    id -= 65536;
    if (id < 65536)  { convW_one(Wv, g_WqkvT, 256, 256, id, 512, 512); return; }
    id -= 65536;
    if (id < 65536)  { convW_one(Wp, g_WpT, 256, 256, id, 0, 512); return; }
    id -= 65536;
    if (id < 768) {
        float v = (id < 256) ? bq[id] : (id < 512 ? bk[id - 256] : bv[id - 512]);
        g_bqkv[id] = v;
        return;
    }
    id -= 768;
    if (id < BATCH * EMB) g_pool[id] = 0.f;
}

__global__ void extractBoth_kernel(const float* __restrict__ x) {
    int id = blockIdx.x * 256 + threadIdx.x;
    if (id < M_PE * 768) {
        int col = id % 768, rw = id / 768;
        int b = rw / NP, pi = rw % NP;
        int ph = pi / 14, pw = pi % 14;
        int c = col % 3, s = col / 3;
        int pc = s % 16, pr = s / 16;
        float v = x[(size_t)(b * 3 + c) * 50176 + (ph * 16 + pr) * 224 + (pw * 16 + pc)];
        __nv_bfloat16 hi, lo; split2(v, hi, lo);
        size_t base = (size_t)rw * 1536;
        g_A1[base + col] = hi; g_A1[base + 768 + col] = lo;
        return;
    }
    id -= M_PE * 768;
    if (id < M_PE * 192) {
        int col = id % 192, rw = id / 192;
        int b = rw / NP, j = rw % NP;
        int q = 4 * j + 3;
        int ph = q / 28, pw = q % 28;
        int c = col % 3, s = col / 3;
        int pc = s % 8, pr = s / 8;
        float v = x[(size_t)(b * 3 + c) * 50176 + (ph * 8 + pr) * 224 + (pw * 8 + pc)];
        __nv_bfloat16 hi, lo; split2(v, hi, lo);
        size_t base = (size_t)rw * 384;
        g_A2[base + col] = hi; g_A2[base + 192 + col] = lo;
    }
}

__device__ __forceinline__ float blockReduce(float v, float* sh, bool ismax) {
    int lane = threadIdx.x & 31, w = threadIdx.x >> 5;
    int nw = blockDim.x >> 5;
    #pragma unroll
    for (int o = 16; o; o >>= 1) {
        float t = __shfl_down_sync(0xffffffffu, v, o);
        v = ismax ? fmaxf(v, t) : v + t;
    }
    if (lane == 0) sh[w] = v;
    __syncthreads();
    if (w == 0) {
        v = (lane < nw) ? sh[lane] : (ismax ? -INFINITY : 0.f);
        #pragma unroll
        for (int o = 16; o; o >>= 1) {
            float t = __shfl_down_sync(0xffffffffu, v, o);
            v = ismax ? fmaxf(v, t) : v + t;
        }
        if (lane == 0) sh[0] = v;
    }
    __syncthreads();
    float r = sh[0];
    __syncthreads();
    return r;
}

__global__ void buildZ_ln_kernel(const float* __restrict__ cls1, const float* __restrict__ cls2,
                                 const float* __restrict__ gam, const float* __restrict__ bet) {
    __shared__ float sh[8];
    int tg = blockIdx.x, e = threadIdx.x;
    int t = tg % NTOK, b = tg / NTOK;
    float v;
    if (t == 0)        v = cls2[e];
    else if (t < 197)  v = g_E2[(size_t)(b * NP + (t - 1)) * EMB + e];
    else if (t == 197) v = cls1[e];
    else               v = g_E1[(size_t)(b * NP + (t - 198)) * EMB + e];
    g_Z[(size_t)tg * EMB + e] = v;
    float m = blockReduce(v, sh, false) * (1.f / EMB);
    float d = v - m;
    float var = blockReduce(d * d, sh, false) * (1.f / EMB);
    float y = d * rsqrtf(var + 1e-5f) * gam[e] + bet[e];
    __nv_bfloat16 hi, lo; split2(y, hi, lo);
    size_t base = (size_t)tg * 512;
    g_Hs[base + e] = hi; g_Hs[base + 256 + e] = lo;
}

// warp-per-row single-pass softmax (/16) + split write
__global__ void softmax_split_kernel() {
    int gw = blockIdx.x * 8 + (threadIdx.x >> 5);
    int lane = threadIdx.x & 31;
    int zz = gw / NTOK, q = gw - zz * NTOK;
    const float* row = g_S + ((size_t)zz * NTOK + q) * SLD;
    float vals[14];
    float mx = -INFINITY;
    #pragma unroll
    for (int i = 0; i < 14; i++) {
        int t = lane + 32 * i;
        vals[i] = (t < NTOK) ? row[t] : -INFINITY;
        mx = fmaxf(mx, vals[i]);
    }
    #pragma unroll
    for (int o = 16; o; o >>= 1) mx = fmaxf(mx, __shfl_xor_sync(0xffffffffu, mx, o));
    float sum = 0.f;
    #pragma unroll
    for (int i = 0; i < 14; i++) {
        float ev = expf(vals[i] - mx);   // expf(-inf)=0 for padded slots
        vals[i] = ev;
        sum += ev;
    }
    #pragma unroll
    for (int o = 16; o; o >>= 1) sum += __shfl_xor_sync(0xffffffffu, sum, o);
    float inv = 1.f / (sum * 16.f);
    __nv_bfloat16* prow = g_Ps + ((size_t)zz * NTOK + q) * 896;
    #pragma unroll
    for (int i = 0; i < 14; i++) {
        int t = lane + 32 * i;
        __nv_bfloat16 hi, lo; split2(vals[i] * inv, hi, lo);
        prow[t] = hi; prow[448 + t] = lo;
    }
}

// LN2 + residual + pooled accumulation (8 tokens per block, one atomicAdd per block)
__global__ void lnres_pool_kernel(const float* __restrict__ gam, const float* __restrict__ bet) {
    __shared__ float sh[8];
    int b = blockIdx.y, e = threadIdx.x;
    float le = 0.f;
    #pragma unroll
    for (int i = 0; i < 8; i++) {
        int t = blockIdx.x * 8 + i;
        if (t < NTOK) {
            size_t idx = ((size_t)b * NTOK + t) * EMB + e;
            float v = g_P[idx];
            float m = blockReduce(v, sh, false) * (1.f / EMB);
            float d = v - m;
            float var = blockReduce(d * d, sh, false) * (1.f / EMB);
            float o = d * rsqrtf(var + 1e-5f) * gam[e] + bet[e];
            le += g_Z[idx] + o;
        }
    }
    atomicAdd(&g_pool[b * EMB + e], le);
}

__global__ void head_kernel(const float* __restrict__ gam, const float* __restrict__ bet,
                            const float* __restrict__ Wc, const float* __restrict__ bc,
                            float* __restrict__ out) {
    __shared__ float sh[8];
    int bb = blockIdx.x, e = threadIdx.x;
    float pooled = g_pool[bb * EMB + e] * (1.f / NTOK);
    float m = blockReduce(pooled, sh, false) * (1.f / EMB);
    float d = pooled - m;
    float var = blockReduce(d * d, sh, false) * (1.f / EMB);
    float y = d * rsqrtf(var + 1e-5f) * gam[e] + bet[e];
    float p0 = blockReduce(y * Wc[e * 2 + 0], sh, false);
    float p1 = blockReduce(y * Wc[e * 2 + 1], sh, false);
    if (e == 0) {
        float l0 = p0 + bc[0], l1 = p1 + bc[1];
        float mm = fmaxf(l0, l1);
        float lse = mm + logf(expf(l0 - mm) + expf(l1 - mm));
        out[bb * 2 + 0] = l0 - lse;
        out[bb * 2 + 1] = l1 - lse;
    }
}

// ================ launch ================
extern "C" void kernel_launch(void* const* d_in, const int* in_sizes, int n_in,
                              void* d_out, int out_size)
{
    const float* x    = (const float*)d_in[0];
    const float* W1   = (const float*)d_in[1];
    const float* b1   = (const float*)d_in[2];
    const float* cls1 = (const float*)d_in[3];
    const float* W2   = (const float*)d_in[4];
    const float* b2   = (const float*)d_in[5];
    const float* cls2 = (const float*)d_in[6];
    const float* ln1g = (const float*)d_in[7];
    const float* ln1b = (const float*)d_in[8];
    const float* Wq   = (const float*)d_in[9];
    const float* bq   = (const float*)d_in[10];
    const float* Wk   = (const float*)d_in[11];
    const float* bk   = (const float*)d_in[12];
    const float* Wv   = (const float*)d_in[13];
    const float* bv   = (const float*)d_in[14];
    const float* Wp   = (const float*)d_in[15];
    const float* bp   = (const float*)d_in[16];
    const float* ln2g = (const float*)d_in[17];
    const float* ln2b = (const float*)d_in[18];
    const float* lncg = (const float*)d_in[19];
    const float* lncb = (const float*)d_in[20];
    const float* Wc   = (const float*)d_in[21];
    const float* bc   = (const float*)d_in[22];
    float* out = (float*)d_out;

    __nv_bfloat16 *A1, *A2, *W1T, *W2T, *WqkvT, *WpT, *Hs, *Qs, *Ks, *Vt, *Ps, *Os;
    float *bqkv, *S, *P, *E1, *E2;
    cudaGetSymbolAddress((void**)&A1, g_A1);
    cudaGetSymbolAddress((void**)&A2, g_A2);
    cudaGetSymbolAddress((void**)&W1T, g_W1T);
    cudaGetSymbolAddress((void**)&W2T, g_W2T);
    cudaGetSymbolAddress((void**)&WqkvT, g_WqkvT);
    cudaGetSymbolAddress((void**)&WpT, g_WpT);
    cudaGetSymbolAddress((void**)&bqkv, g_bqkv);
    cudaGetSymbolAddress((void**)&Hs, g_Hs);
    cudaGetSymbolAddress((void**)&Qs, g_Qs);
    cudaGetSymbolAddress((void**)&Ks, g_Ks);
    cudaGetSymbolAddress((void**)&Vt, g_Vt);
    cudaGetSymbolAddress((void**)&S, g_S);
    cudaGetSymbolAddress((void**)&Ps, g_Ps);
    cudaGetSymbolAddress((void**)&Os, g_Os);
    cudaGetSymbolAddress((void**)&P, g_P);
    cudaGetSymbolAddress((void**)&E1, g_E1);
    cudaGetSymbolAddress((void**)&E2, g_E2);

    cudaFuncSetAttribute(gemm_mma, cudaFuncAttributeMaxDynamicSharedMemorySize, GSMEM);

    // 1: weight conversions + pool zero
    convAll_kernel<<<(541440 + 255)/256, 256>>>(W1, W2, Wq, Wk, Wv, Wp, bq, bk, bv);
    // 2: patch extracts
    extractBoth_kernel<<<(M_PE*960 + 255)/256, 256>>>(x);
    // 3,4: patch-embed GEMMs
    gemm_mma<<<dim3(2,196,1), 256, GSMEM>>>(A1, W1T, b1, E1,
        M_PE, 256, 2304, 1536, 1536, 256, 1536, 768, 0, 0,0,0,0,0,0);
    gemm_mma<<<dim3(2,196,1), 256, GSMEM>>>(A2, W2T, b2, E2,
        M_PE, 256, 576, 384, 384, 256, 384, 192, 0, 0,0,0,0,0,0);
    // 5: fused z-assembly + LN + split
    buildZ_ln_kernel<<<M_TOK, 256>>>(cls1, cls2, ln1g, ln1b);
    // 6: fused QKV GEMM with Q/K/V split epilogue (V transposed into g_Vt)
    gemm_mma<<<dim3(6,394,1), 256, GSMEM>>>(Hs, WqkvT, bqkv, Qs,
        M_TOK, 768, 768, 512, 512, 768, 512, 256, 3, 0,0,0,0,0,0);
    // 7: S = Q @ K^T
    gemm_mma<<<dim3(4,4,256), 256, GSMEM>>>(Qs, Ks, nullptr, S,
        NTOK, NTOK, 384, 256, 256, SLD, 256, 128, 0,
        2L*NTOK*256, (long)NTOK*256, 2L*NTOK*256, (long)NTOK*256,
        2L*NTOK*SLD, (long)NTOK*SLD);
    // 8: softmax + split (warp per row)
    softmax_split_kernel<<<(256*NTOK)/8, 256>>>();
    // 9: O = P @ V^T -> split bf16 directly into Os
    gemm_mma<<<dim3(1,4,256), 256, GSMEM>>>(Ps, Vt, nullptr, Os,
        NTOK, 128, 1344, 896, 896, 512, 896, 448, 1,
        2L*NTOK*896, (long)NTOK*896, 2L*128*896, 128L*896,
        (long)NTOK*512, 128L);
    // 10: projection
    gemm_mma<<<dim3(2,394,1), 256, GSMEM>>>(Os, WpT, bp, P,
        M_TOK, 256, 768, 512, 512, 256, 512, 256, 0, 0,0,0,0,0,0);
    // 11,12: LN2+residual+pool, head
    lnres_pool_kernel<<<dim3(50, BATCH), 256>>>(ln2g, ln2b);
    head_kernel<<<BATCH, 256>>>(lncg, lncb, Wc, bc, out);
}

// round 10
// speedup vs baseline: 1.2191x; 1.0376x over previous
#include <cuda_runtime.h>
#include <cuda_bf16.h>
#include <cstdint>
#include <math.h>

#define BATCH 128
#define EMB   256
#define NTOK  394
#define NP    196
#define M_PE  (BATCH*NP)
#define M_TOK (BATCH*NTOK)
#define SLD   400
#define NT_PAD 448
#define AST   40
#define TILEB (128*AST*2)
#define NSTG  4
#define GSMEM (NSTG*2*TILEB)        // 81920 B dynamic smem

// ---------------- scratch ([hi|lo] split storage) ----------------
__device__ __nv_bfloat16 g_A1[(size_t)M_PE*1536];
__device__ __nv_bfloat16 g_A2[(size_t)M_PE*384];
__device__ __nv_bfloat16 g_W1T[256*1536];
__device__ __nv_bfloat16 g_W2T[256*384];
__device__ __nv_bfloat16 g_WqkvT[768*512];
__device__ __nv_bfloat16 g_WpT[256*512];
__device__ float g_bqkv[768];
__device__ float g_E1[(size_t)M_PE*EMB];
__device__ float g_E2[(size_t)M_PE*EMB];
__device__ float g_Z [(size_t)M_TOK*EMB];
__device__ __nv_bfloat16 g_Hs[(size_t)M_TOK*512];
__device__ __nv_bfloat16 g_Qs[(size_t)256*NTOK*256];
__device__ __nv_bfloat16 g_Ks[(size_t)256*NTOK*256];
__device__ __nv_bfloat16 g_Vt[(size_t)256*128*896];
__device__ float g_S [(size_t)256*NTOK*SLD];
__device__ __nv_bfloat16 g_Ps[(size_t)256*NTOK*896];
__device__ __nv_bfloat16 g_Os[(size_t)M_TOK*512];
__device__ float g_P [(size_t)M_TOK*EMB];
__device__ float g_pool[BATCH*EMB];

__device__ __forceinline__ uint32_t smem_u32(const void* p) {
    uint32_t a;
    asm("{ .reg .u64 t; cvta.to.shared.u64 t, %1; cvt.u32.u64 %0, t; }" : "=r"(a) : "l"(p));
    return a;
}
__device__ __forceinline__ void ldm4(uint32_t* r, uint32_t addr) {
    asm volatile("ldmatrix.sync.aligned.m8n8.x4.shared.b16 {%0,%1,%2,%3}, [%4];"
        : "=r"(r[0]), "=r"(r[1]), "=r"(r[2]), "=r"(r[3]) : "r"(addr));
}
__device__ __forceinline__ void mma16816(float* c, const uint32_t* a, uint32_t b0, uint32_t b1) {
    asm volatile(
        "mma.sync.aligned.m16n8k16.row.col.f32.bf16.bf16.f32 "
        "{%0,%1,%2,%3}, {%4,%5,%6,%7}, {%8,%9}, {%0,%1,%2,%3};"
        : "+f"(c[0]), "+f"(c[1]), "+f"(c[2]), "+f"(c[3])
        : "r"(a[0]), "r"(a[1]), "r"(a[2]), "r"(a[3]), "r"(b0), "r"(b1));
}
__device__ __forceinline__ void cp16(uint32_t dst, const void* src, bool pred) {
    int sz = pred ? 16 : 0;
    asm volatile("cp.async.cg.shared.global [%0], [%1], 16, %2;"
        :: "r"(dst), "l"(src), "r"(sz));
}
#define CP_COMMIT() asm volatile("cp.async.commit_group;" ::: "memory")
#define CP_WAIT0()  asm volatile("cp.async.wait_group 0;" ::: "memory")
#define CP_WAIT1()  asm volatile("cp.async.wait_group 1;" ::: "memory")
#define CP_WAIT2()  asm volatile("cp.async.wait_group 2;" ::: "memory")

__device__ __forceinline__ void split2(float v, __nv_bfloat16& hi, __nv_bfloat16& lo) {
    hi = __float2bfloat16(v);
    lo = __float2bfloat16(v - __bfloat162float(hi));
}
__device__ __forceinline__ uint16_t bfu(__nv_bfloat16 h) {
    return __bfloat16_as_ushort(h);
}

// ============ warp-MMA GEMM, K-chunk 32, 4-stage cp.async + wrap addressing ============
// outMode 0: fp32 C (+bias). outMode 1: split bf16 C (hi col c, lo col 256+c).
// outMode 3: fused QKV epilogue (Q/K -> g_Qs/g_Ks per-head split; V -> g_Vt transposed split).
__global__ void __launch_bounds__(256) gemm_mma(
    const __nv_bfloat16* __restrict__ Ag, const __nv_bfloat16* __restrict__ Bg,
    const float* __restrict__ bias, void* __restrict__ Cg,
    int M, int N, int K, int lda, int ldb, int ldc, int awrap, int bwrap, int outMode,
    long sAz2, long sAz1, long sBz2, long sBz1, long sCz2, long sCz1)
{
    extern __shared__ char sm[];
    uint32_t sbase = smem_u32(sm);

    int tid = threadIdx.x, wid = tid >> 5, lane = tid & 31;
    int z = blockIdx.z;
    const __nv_bfloat16* A = Ag + (long)(z >> 1) * sAz2 + (long)(z & 1) * sAz1;
    const __nv_bfloat16* B = Bg + (long)(z >> 1) * sBz2 + (long)(z & 1) * sBz1;
    int row0 = blockIdx.y * 128, col0 = blockIdx.x * 128;
    A += (size_t)row0 * lda;
    B += (size_t)col0 * ldb;
    int esz = (outMode == 1) ? 2 : 4;
    char* Cb = (char*)Cg + ((long)(z >> 1) * sCz2 + (long)(z & 1) * sCz1
                            + (size_t)row0 * ldc + col0) * esz;
    int Mrem = M - row0, Nrem = N - col0;

    int wm = wid & 3, wn = wid >> 2;
    bool wact = (wm * 32 < Mrem) && (wn * 64 < Nrem);

    int ldrow = tid >> 1, half = tid & 1;
    bool aval = ldrow < Mrem, bval = ldrow < Nrem;
    const char* gaBase = reinterpret_cast<const char*>(A + (size_t)ldrow * lda) + half * 32;
    const char* gbBase = reinterpret_cast<const char*>(B + (size_t)ldrow * ldb) + half * 32;
    uint32_t dstOff = ldrow * (AST * 2) + half * 32;

    uint32_t aoff = ((wm * 32 + (lane & 15)) * AST + ((lane >> 4) * 8)) * 2;
    uint32_t boff = ((wn * 64 + (lane & 7) + ((lane >> 4) & 1) * 8) * AST) * 2
                  + ((lane >> 3) & 1) * 16;

    float acc[2][8][4];
    #pragma unroll
    for (int i = 0; i < 2; i++)
        #pragma unroll
        for (int j = 0; j < 8; j++)
            #pragma unroll
            for (int t = 0; t < 4; t++) acc[i][j][t] = 0.f;

    int nchunk = K >> 5;

    #pragma unroll
    for (int p = 0; p < 3; p++) {
        int koff = p * 32;
        int ka = koff >= awrap ? koff - awrap : koff;
        int kb = koff >= bwrap ? koff - bwrap : koff;
        uint32_t dA = sbase + p * 2 * TILEB + dstOff;
        uint32_t dB = dA + TILEB;
        cp16(dA, gaBase + (size_t)ka * 2, aval);
        cp16(dA + 16, gaBase + (size_t)ka * 2 + 16, aval);
        cp16(dB, gbBase + (size_t)kb * 2, bval);
        cp16(dB + 16, gbBase + (size_t)kb * 2 + 16, bval);
        CP_COMMIT();
    }

    for (int i = 0; i < nchunk; i++) {
        if (i + 3 <= nchunk)      { CP_WAIT2(); }
        else if (i + 2 == nchunk) { CP_WAIT1(); }
        else                      { CP_WAIT0(); }
        __syncthreads();

        int st = i & 3;
        uint32_t sA = sbase + st * 2 * TILEB;
        uint32_t sB = sA + TILEB;
        if (wact) {
            #pragma unroll
            for (int kk = 0; kk < 2; kk++) {
                uint32_t a0[4], a1[4], bf[4][4];
                ldm4(a0, sA + aoff + kk * 32);
                ldm4(a1, sA + aoff + 16 * AST * 2 + kk * 32);
                #pragma unroll
                for (int j = 0; j < 4; j++)
                    ldm4(bf[j], sB + boff + j * 16 * AST * 2 + kk * 32);
                #pragma unroll
                for (int j = 0; j < 4; j++) {
                    mma16816(acc[0][2*j],   a0, bf[j][0], bf[j][1]);
                    mma16816(acc[0][2*j+1], a0, bf[j][2], bf[j][3]);
                    mma16816(acc[1][2*j],   a1, bf[j][0], bf[j][1]);
                    mma16816(acc[1][2*j+1], a1, bf[j][2], bf[j][3]);
                }
            }
        }
        if (i + 3 < nchunk) {
            int koff = (i + 3) * 32;
            int ka = koff >= awrap ? koff - awrap : koff;
            int kb = koff >= bwrap ? koff - bwrap : koff;
            int st2 = (i + 3) & 3;
            uint32_t dA = sbase + st2 * 2 * TILEB + dstOff;
            uint32_t dB = dA + TILEB;
            cp16(dA, gaBase + (size_t)ka * 2, aval);
            cp16(dA + 16, gaBase + (size_t)ka * 2 + 16, aval);
            cp16(dB, gbBase + (size_t)kb * 2, bval);
            cp16(dB + 16, gbBase + (size_t)kb * 2 + 16, bval);
            CP_COMMIT();
        }
    }

    if (!wact) return;
    int grp = lane >> 2, qd = lane & 3;

    if (outMode == 0) {
        float* C = (float*)Cb;
        #pragma unroll
        for (int mt = 0; mt < 2; mt++) {
            int r0 = wm * 32 + mt * 16 + grp;
            #pragma unroll
            for (int nt = 0; nt < 8; nt++) {
                int c = wn * 64 + nt * 8 + qd * 2;
                float b0v = 0.f, b1v = 0.f;
                if (bias && c < Nrem)     b0v = bias[col0 + c];
                if (bias && c + 1 < Nrem) b1v = bias[col0 + c + 1];
                if (r0 < Mrem) {
                    if (c < Nrem)     C[(size_t)r0 * ldc + c]     = acc[mt][nt][0] + b0v;
                    if (c + 1 < Nrem) C[(size_t)r0 * ldc + c + 1] = acc[mt][nt][1] + b1v;
                }
                if (r0 + 8 < Mrem) {
                    if (c < Nrem)     C[(size_t)(r0 + 8) * ldc + c]     = acc[mt][nt][2] + b0v;
                    if (c + 1 < Nrem) C[(size_t)(r0 + 8) * ldc + c + 1] = acc[mt][nt][3] + b1v;
                }
            }
        }
    } else if (outMode == 1) {
        __nv_bfloat16* C = (__nv_bfloat16*)Cb;
        #pragma unroll
        for (int mt = 0; mt < 2; mt++) {
            int r0 = wm * 32 + mt * 16 + grp;
            #pragma unroll
            for (int nt = 0; nt < 8; nt++) {
                int c = wn * 64 + nt * 8 + qd * 2;
                #pragma unroll
                for (int e = 0; e < 4; e++) {
                    int rr = r0 + (e >> 1) * 8;
                    int cc = c + (e & 1);
                    if (rr < Mrem && cc < Nrem) {
                        __nv_bfloat16 hi, lo; split2(acc[mt][nt][e], hi, lo);
                        C[(size_t)rr * ldc + cc] = hi;
                        C[(size_t)rr * ldc + 256 + cc] = lo;
                    }
                }
            }
        }
    } else { // outMode 3
        #pragma unroll
        for (int mt = 0; mt < 2; mt++) {
            int r0 = wm * 32 + mt * 16 + grp;
            #pragma unroll
            for (int nt = 0; nt < 8; nt++) {
                int c = wn * 64 + nt * 8 + qd * 2;
                #pragma unroll
                for (int e = 0; e < 4; e++) {
                    int rr = r0 + (e >> 1) * 8;
                    int cc = c + (e & 1);
                    if (rr < Mrem) {
                        int gc = col0 + cc;
                        float val = acc[mt][nt][e] + bias[gc];
                        int gm = row0 + rr;
                        int b = gm / NTOK, t = gm - b * NTOK;
                        int h = (gc >> 7) & 1;
                        int d = gc & 127;
                        __nv_bfloat16 hi, lo; split2(val, hi, lo);
                        if (gc < 512) {
                            size_t base = ((size_t)(b * 2 + h) * NTOK + t) * 256;
                            __nv_bfloat16* dst = (gc < 256) ? g_Qs : g_Ks;
                            dst[base + d] = hi; dst[base + 128 + d] = lo;
                        } else {
                            size_t base = ((size_t)(b * 2 + h) * 128 + d) * 896 + t;
                            g_Vt[base] = hi; g_Vt[base + 448] = lo;
                        }
                    }
                }
            }
        }
    }
}

// ================ conversion / pointwise kernels ================
__device__ __forceinline__ void convW_one(const float* W, __nv_bfloat16* out,
                                          int K, int N, int id, int nOff, int ldout) {
    int k = id / N, n = id % N;
    __nv_bfloat16 hi, lo; split2(W[(size_t)k * N + n], hi, lo);
    size_t base = (size_t)(nOff + n) * ldout;
    out[base + k] = hi; out[base + K + k] = lo;
}

__global__ void convAll_kernel(const float* __restrict__ W1, const float* __restrict__ W2,
                               const float* __restrict__ Wq, const float* __restrict__ Wk,
                               const float* __restrict__ Wv, const float* __restrict__ Wp,
                               const float* __restrict__ bq, const float* __restrict__ bk,
                               const float* __restrict__ bv) {
    int id = blockIdx.x * 256 + threadIdx.x;
    if (id < 196608) { convW_one(W1, g_W1T, 768, 256, id, 0, 1536); return; }
    id -= 196608;
    if (id < 49152)  { convW_one(W2, g_W2T, 192, 256, id, 0, 384); return; }
    id -= 49152;
    if (id < 65536)  { convW_one(Wq, g_WqkvT, 256, 256, id, 0, 512); return; }
    id -= 65536;
    if (id < 65536)  { convW_one(Wk, g_WqkvT, 256, 256, id, 256, 512); return; }
    id -= 65536;
    if (id < 65536)  { convW_one(Wv, g_WqkvT, 256, 256, id, 512, 512); return; }
    id -= 65536;
    if (id < 65536)  { convW_one(Wp, g_WpT, 256, 256, id, 0, 512); return; }
    id -= 65536;
    if (id < 768) {
        float v = (id < 256) ? bq[id] : (id < 512 ? bk[id - 256] : bv[id - 512]);
        g_bqkv[id] = v;
        return;
    }
    id -= 768;
    if (id < BATCH * EMB) g_pool[id] = 0.f;
}

__global__ void extractBoth_kernel(const float* __restrict__ x) {
    int id = blockIdx.x * 256 + threadIdx.x;
    if (id < M_PE * 768) {
        int col = id % 768, rw = id / 768;
        int b = rw / NP, pi = rw % NP;
        int ph = pi / 14, pw = pi % 14;
        int c = col % 3, s = col / 3;
        int pc = s % 16, pr = s / 16;
        float v = x[(size_t)(b * 3 + c) * 50176 + (ph * 16 + pr) * 224 + (pw * 16 + pc)];
        __nv_bfloat16 hi, lo; split2(v, hi, lo);
        size_t base = (size_t)rw * 1536;
        g_A1[base + col] = hi; g_A1[base + 768 + col] = lo;
        return;
    }
    id -= M_PE * 768;
    if (id < M_PE * 192) {
        int col = id % 192, rw = id / 192;
        int b = rw / NP, j = rw % NP;
        int q = 4 * j + 3;
        int ph = q / 28, pw = q % 28;
        int c = col % 3, s = col / 3;
        int pc = s % 8, pr = s / 8;
        float v = x[(size_t)(b * 3 + c) * 50176 + (ph * 8 + pr) * 224 + (pw * 8 + pc)];
        __nv_bfloat16 hi, lo; split2(v, hi, lo);
        size_t base = (size_t)rw * 384;
        g_A2[base + col] = hi; g_A2[base + 192 + col] = lo;
    }
}

// warp-per-token: build z row, store Z, LN via shuffle, split -> Hs (vectorized)
__global__ void buildZ_ln_kernel(const float* __restrict__ cls1, const float* __restrict__ cls2,
                                 const float* __restrict__ gam, const float* __restrict__ bet) {
    int w = threadIdx.x >> 5, lane = threadIdx.x & 31;
    int tg = blockIdx.x * 8 + w;
    if (tg >= M_TOK) return;
    int t = tg % NTOK, b = tg / NTOK;
    const float* src;
    if (t == 0)        src = cls2;
    else if (t < 197)  src = g_E2 + (size_t)(b * NP + (t - 1)) * EMB;
    else if (t == 197) src = cls1;
    else               src = g_E1 + (size_t)(b * NP + (t - 198)) * EMB;
    int e0 = lane * 8;
    float4 v0 = *reinterpret_cast<const float4*>(src + e0);
    float4 v1 = *reinterpret_cast<const float4*>(src + e0 + 4);
    float v[8] = {v0.x, v0.y, v0.z, v0.w, v1.x, v1.y, v1.z, v1.w};
    // store Z
    float* zp = g_Z + (size_t)tg * EMB + e0;
    *reinterpret_cast<float4*>(zp) = v0;
    *reinterpret_cast<float4*>(zp + 4) = v1;
    // mean
    float s = 0.f;
    #pragma unroll
    for (int j = 0; j < 8; j++) s += v[j];
    #pragma unroll
    for (int o = 16; o; o >>= 1) s += __shfl_xor_sync(0xffffffffu, s, o);
    float m = s * (1.f / EMB);
    float vs = 0.f;
    #pragma unroll
    for (int j = 0; j < 8; j++) { float d = v[j] - m; vs += d * d; }
    #pragma unroll
    for (int o = 16; o; o >>= 1) vs += __shfl_xor_sync(0xffffffffu, vs, o);
    float rstd = rsqrtf(vs * (1.f / EMB) + 1e-5f);
    float4 g0 = *reinterpret_cast<const float4*>(gam + e0);
    float4 g1 = *reinterpret_cast<const float4*>(gam + e0 + 4);
    float4 b0 = *reinterpret_cast<const float4*>(bet + e0);
    float4 b1 = *reinterpret_cast<const float4*>(bet + e0 + 4);
    float gm[8] = {g0.x, g0.y, g0.z, g0.w, g1.x, g1.y, g1.z, g1.w};
    float bt[8] = {b0.x, b0.y, b0.z, b0.w, b1.x, b1.y, b1.z, b1.w};
    uint32_t hw[4], lw[4];
    #pragma unroll
    for (int j = 0; j < 4; j++) {
        float y0 = (v[2*j] - m) * rstd * gm[2*j] + bt[2*j];
        float y1 = (v[2*j+1] - m) * rstd * gm[2*j+1] + bt[2*j+1];
        __nv_bfloat16 h0, l0, h1, l1;
        split2(y0, h0, l0); split2(y1, h1, l1);
        hw[j] = (uint32_t)bfu(h0) | ((uint32_t)bfu(h1) << 16);
        lw[j] = (uint32_t)bfu(l0) | ((uint32_t)bfu(l1) << 16);
    }
    __nv_bfloat16* hp = g_Hs + (size_t)tg * 512 + e0;
    *reinterpret_cast<uint4*>(hp) = make_uint4(hw[0], hw[1], hw[2], hw[3]);
    *reinterpret_cast<uint4*>(hp + 256) = make_uint4(lw[0], lw[1], lw[2], lw[3]);
}

// warp-per-row single-pass softmax (/16) + split write
__global__ void softmax_split_kernel() {
    int gw = blockIdx.x * 8 + (threadIdx.x >> 5);
    int lane = threadIdx.x & 31;
    int zz = gw / NTOK, q = gw - zz * NTOK;
    const float* row = g_S + ((size_t)zz * NTOK + q) * SLD;
    float vals[14];
    float mx = -INFINITY;
    #pragma unroll
    for (int i = 0; i < 14; i++) {
        int t = lane + 32 * i;
        vals[i] = (t < NTOK) ? row[t] : -INFINITY;
        mx = fmaxf(mx, vals[i]);
    }
    #pragma unroll
    for (int o = 16; o; o >>= 1) mx = fmaxf(mx, __shfl_xor_sync(0xffffffffu, mx, o));
    float sum = 0.f;
    #pragma unroll
    for (int i = 0; i < 14; i++) {
        float ev = expf(vals[i] - mx);
        vals[i] = ev;
        sum += ev;
    }
    #pragma unroll
    for (int o = 16; o; o >>= 1) sum += __shfl_xor_sync(0xffffffffu, sum, o);
    float inv = 1.f / (sum * 16.f);
    __nv_bfloat16* prow = g_Ps + ((size_t)zz * NTOK + q) * 896;
    #pragma unroll
    for (int i = 0; i < 14; i++) {
        int t = lane + 32 * i;
        __nv_bfloat16 hi, lo; split2(vals[i] * inv, hi, lo);
        prow[t] = hi; prow[448 + t] = lo;
    }
}

// warp-per-token LN2 + residual + smem pool accumulation + one global atomic per elem per block
__global__ void lnres_pool_kernel(const float* __restrict__ gam, const float* __restrict__ bet) {
    __shared__ float acc[256];
    int w = threadIdx.x >> 5, lane = threadIdx.x & 31;
    acc[threadIdx.x] = 0.f;
    __syncthreads();
    int b = blockIdx.y;
    int t = blockIdx.x * 8 + w;
    if (t < NTOK) {
        int e0 = lane * 8;
        size_t idx = ((size_t)b * NTOK + t) * EMB + e0;
        float4 p0 = *reinterpret_cast<const float4*>(g_P + idx);
        float4 p1 = *reinterpret_cast<const float4*>(g_P + idx + 4);
        float v[8] = {p0.x, p0.y, p0.z, p0.w, p1.x, p1.y, p1.z, p1.w};
        float s = 0.f;
        #pragma unroll
        for (int j = 0; j < 8; j++) s += v[j];
        #pragma unroll
        for (int o = 16; o; o >>= 1) s += __shfl_xor_sync(0xffffffffu, s, o);
        float m = s * (1.f / EMB);
        float vs = 0.f;
        #pragma unroll
        for (int j = 0; j < 8; j++) { float d = v[j] - m; vs += d * d; }
        #pragma unroll
        for (int o = 16; o; o >>= 1) vs += __shfl_xor_sync(0xffffffffu, vs, o);
        float rstd = rsqrtf(vs * (1.f / EMB) + 1e-5f);
        float4 z0 = *reinterpret_cast<const float4*>(g_Z + idx);
        float4 z1 = *reinterpret_cast<const float4*>(g_Z + idx + 4);
        float zv[8] = {z0.x, z0.y, z0.z, z0.w, z1.x, z1.y, z1.z, z1.w};
        float4 g0 = *reinterpret_cast<const float4*>(gam + e0);
        float4 g1 = *reinterpret_cast<const float4*>(gam + e0 + 4);
        float4 bb0 = *reinterpret_cast<const float4*>(bet + e0);
        float4 bb1 = *reinterpret_cast<const float4*>(bet + e0 + 4);
        float gmv[8] = {g0.x, g0.y, g0.z, g0.w, g1.x, g1.y, g1.z, g1.w};
        float btv[8] = {bb0.x, bb0.y, bb0.z, bb0.w, bb1.x, bb1.y, bb1.z, bb1.w};
        #pragma unroll
        for (int j = 0; j < 8; j++) {
            float o = (v[j] - m) * rstd * gmv[j] + btv[j];
            atomicAdd(&acc[e0 + j], zv[j] + o);
        }
    }
    __syncthreads();
    atomicAdd(&g_pool[b * EMB + threadIdx.x], acc[threadIdx.x]);
}

__device__ __forceinline__ float blockReduceSum(float v, float* sh) {
    int lane = threadIdx.x & 31, w = threadIdx.x >> 5;
    #pragma unroll
    for (int o = 16; o; o >>= 1) v += __shfl_down_sync(0xffffffffu, v, o);
    if (lane == 0) sh[w] = v;
    __syncthreads();
    if (w == 0) {
        v = (lane < 8) ? sh[lane] : 0.f;
        #pragma unroll
        for (int o = 4; o; o >>= 1) v += __shfl_down_sync(0xffffffffu, v, o);
        if (lane == 0) sh[0] = v;
    }
    __syncthreads();
    float r = sh[0];
    __syncthreads();
    return r;
}

__global__ void head_kernel(const float* __restrict__ gam, const float* __restrict__ bet,
                            const float* __restrict__ Wc, const float* __restrict__ bc,
                            float* __restrict__ out) {
    __shared__ float sh[8];
    int bb = blockIdx.x, e = threadIdx.x;
    float pooled = g_pool[bb * EMB + e] * (1.f / NTOK);
    float m = blockReduceSum(pooled, sh) * (1.f / EMB);
    float d = pooled - m;
    float var = blockReduceSum(d * d, sh) * (1.f / EMB);
    float y = d * rsqrtf(var + 1e-5f) * gam[e] + bet[e];
    float p0 = blockReduceSum(y * Wc[e * 2 + 0], sh);
    float p1 = blockReduceSum(y * Wc[e * 2 + 1], sh);
    if (e == 0) {
        float l0 = p0 + bc[0], l1 = p1 + bc[1];
        float mm = fmaxf(l0, l1);
        float lse = mm + logf(expf(l0 - mm) + expf(l1 - mm));
        out[bb * 2 + 0] = l0 - lse;
        out[bb * 2 + 1] = l1 - lse;
    }
}

// ================ launch ================
extern "C" void kernel_launch(void* const* d_in, const int* in_sizes, int n_in,
                              void* d_out, int out_size)
{
    const float* x    = (const float*)d_in[0];
    const float* W1   = (const float*)d_in[1];
    const float* b1   = (const float*)d_in[2];
    const float* cls1 = (const float*)d_in[3];
    const float* W2   = (const float*)d_in[4];
    const float* b2   = (const float*)d_in[5];
    const float* cls2 = (const float*)d_in[6];
    const float* ln1g = (const float*)d_in[7];
    const float* ln1b = (const float*)d_in[8];
    const float* Wq   = (const float*)d_in[9];
    const float* bq   = (const float*)d_in[10];
    const float* Wk   = (const float*)d_in[11];
    const float* bk   = (const float*)d_in[12];
    const float* Wv   = (const float*)d_in[13];
    const float* bv   = (const float*)d_in[14];
    const float* Wp   = (const float*)d_in[15];
    const float* bp   = (const float*)d_in[16];
    const float* ln2g = (const float*)d_in[17];
    const float* ln2b = (const float*)d_in[18];
    const float* lncg = (const float*)d_in[19];
    const float* lncb = (const float*)d_in[20];
    const float* Wc   = (const float*)d_in[21];
    const float* bc   = (const float*)d_in[22];
    float* out = (float*)d_out;

    __nv_bfloat16 *A1, *A2, *W1T, *W2T, *WqkvT, *WpT, *Hs, *Qs, *Ks, *Vt, *Ps, *Os;
    float *bqkv, *S, *P, *E1, *E2;
    cudaGetSymbolAddress((void**)&A1, g_A1);
    cudaGetSymbolAddress((void**)&A2, g_A2);
    cudaGetSymbolAddress((void**)&W1T, g_W1T);
    cudaGetSymbolAddress((void**)&W2T, g_W2T);
    cudaGetSymbolAddress((void**)&WqkvT, g_WqkvT);
    cudaGetSymbolAddress((void**)&WpT, g_WpT);
    cudaGetSymbolAddress((void**)&bqkv, g_bqkv);
    cudaGetSymbolAddress((void**)&Hs, g_Hs);
    cudaGetSymbolAddress((void**)&Qs, g_Qs);
    cudaGetSymbolAddress((void**)&Ks, g_Ks);
    cudaGetSymbolAddress((void**)&Vt, g_Vt);
    cudaGetSymbolAddress((void**)&S, g_S);
    cudaGetSymbolAddress((void**)&Ps, g_Ps);
    cudaGetSymbolAddress((void**)&Os, g_Os);
    cudaGetSymbolAddress((void**)&P, g_P);
    cudaGetSymbolAddress((void**)&E1, g_E1);
    cudaGetSymbolAddress((void**)&E2, g_E2);

    cudaFuncSetAttribute(gemm_mma, cudaFuncAttributeMaxDynamicSharedMemorySize, GSMEM);

    // 1: weight conversions + pool zero
    convAll_kernel<<<(541440 + 255)/256, 256>>>(W1, W2, Wq, Wk, Wv, Wp, bq, bk, bv);
    // 2: patch extracts
    extractBoth_kernel<<<(M_PE*960 + 255)/256, 256>>>(x);
    // 3,4: patch-embed GEMMs
    gemm_mma<<<dim3(2,196,1), 256, GSMEM>>>(A1, W1T, b1, E1,
        M_PE, 256, 2304, 1536, 1536, 256, 1536, 768, 0, 0,0,0,0,0,0);
    gemm_mma<<<dim3(2,196,1), 256, GSMEM>>>(A2, W2T, b2, E2,
        M_PE, 256, 576, 384, 384, 256, 384, 192, 0, 0,0,0,0,0,0);
    // 5: fused z-assembly + LN + split (warp per token)
    buildZ_ln_kernel<<<M_TOK/8, 256>>>(cls1, cls2, ln1g, ln1b);
    // 6: fused QKV GEMM with Q/K/V split epilogue
    gemm_mma<<<dim3(6,394,1), 256, GSMEM>>>(Hs, WqkvT, bqkv, Qs,
        M_TOK, 768, 768, 512, 512, 768, 512, 256, 3, 0,0,0,0,0,0);
    // 7: S = Q @ K^T
    gemm_mma<<<dim3(4,4,256), 256, GSMEM>>>(Qs, Ks, nullptr, S,
        NTOK, NTOK, 384, 256, 256, SLD, 256, 128, 0,
        2L*NTOK*256, (long)NTOK*256, 2L*NTOK*256, (long)NTOK*256,
        2L*NTOK*SLD, (long)NTOK*SLD);
    // 8: softmax + split (warp per row)
    softmax_split_kernel<<<(256*NTOK)/8, 256>>>();
    // 9: O = P @ V^T -> split bf16 into Os
    gemm_mma<<<dim3(1,4,256), 256, GSMEM>>>(Ps, Vt, nullptr, Os,
        NTOK, 128, 1344, 896, 896, 512, 896, 448, 1,
        2L*NTOK*896, (long)NTOK*896, 2L*128*896, 128L*896,
        (long)NTOK*512, 128L);
    // 10: projection
    gemm_mma<<<dim3(2,394,1), 256, GSMEM>>>(Os, WpT, bp, P,
        M_TOK, 256, 768, 512, 512, 256, 512, 256, 0, 0,0,0,0,0,0);
    // 11,12: LN2+residual+pool (warp per token), head
    lnres_pool_kernel<<<dim3(50, BATCH), 256>>>(ln2g, ln2b);
    head_kernel<<<BATCH, 256>>>(lncg, lncb, Wc, bc, out);
}

// round 13
// speedup vs baseline: 1.2503x; 1.0256x over previous
#include <cuda_runtime.h>
#include <cuda_bf16.h>
#include <cstdint>
#include <math.h>

#define BATCH 128
#define EMB   256
#define NTOK  394
#define NP    196
#define M_PE  (BATCH*NP)
#define M_TOK (BATCH*NTOK)
#define SLD   400
#define NT_PAD 448
#define AST   40
#define TILEB (128*AST*2)
#define NSTG  4
#define GSMEM (NSTG*2*TILEB)        // 81920 B dynamic smem

// ---------------- scratch ([hi|lo] split storage) ----------------
__device__ __nv_bfloat16 g_A1[(size_t)M_PE*1536];
__device__ __nv_bfloat16 g_A2[(size_t)M_PE*384];
__device__ __nv_bfloat16 g_W1T[256*1536];
__device__ __nv_bfloat16 g_W2T[256*384];
__device__ __nv_bfloat16 g_WqkvT[768*512];
__device__ __nv_bfloat16 g_WpT[256*512];
__device__ float g_bqkv[768];
__device__ float g_E1[(size_t)M_PE*EMB];
__device__ float g_E2[(size_t)M_PE*EMB];
__device__ float g_Z [(size_t)M_TOK*EMB];
__device__ __nv_bfloat16 g_Hs[(size_t)M_TOK*512];
__device__ __nv_bfloat16 g_Qs[(size_t)256*NTOK*256];
__device__ __nv_bfloat16 g_Ks[(size_t)256*NTOK*256];
__device__ __nv_bfloat16 g_Vt[(size_t)256*128*896];
__device__ float g_S [(size_t)256*NTOK*SLD];
__device__ __nv_bfloat16 g_Ps[(size_t)256*NTOK*896];
__device__ __nv_bfloat16 g_Os[(size_t)M_TOK*512];
__device__ float g_P [(size_t)M_TOK*EMB];
__device__ float g_pool[BATCH*EMB];

__device__ __forceinline__ uint32_t smem_u32(const void* p) {
    uint32_t a;
    asm("{ .reg .u64 t; cvta.to.shared.u64 t, %1; cvt.u32.u64 %0, t; }" : "=r"(a) : "l"(p));
    return a;
}
__device__ __forceinline__ void ldm4(uint32_t* r, uint32_t addr) {
    asm volatile("ldmatrix.sync.aligned.m8n8.x4.shared.b16 {%0,%1,%2,%3}, [%4];"
        : "=r"(r[0]), "=r"(r[1]), "=r"(r[2]), "=r"(r[3]) : "r"(addr));
}
__device__ __forceinline__ void mma16816(float* c, const uint32_t* a, uint32_t b0, uint32_t b1) {
    asm volatile(
        "mma.sync.aligned.m16n8k16.row.col.f32.bf16.bf16.f32 "
        "{%0,%1,%2,%3}, {%4,%5,%6,%7}, {%8,%9}, {%0,%1,%2,%3};"
        : "+f"(c[0]), "+f"(c[1]), "+f"(c[2]), "+f"(c[3])
        : "r"(a[0]), "r"(a[1]), "r"(a[2]), "r"(a[3]), "r"(b0), "r"(b1));
}
__device__ __forceinline__ void cp16(uint32_t dst, const void* src, bool pred) {
    int sz = pred ? 16 : 0;
    asm volatile("cp.async.cg.shared.global [%0], [%1], 16, %2;"
        :: "r"(dst), "l"(src), "r"(sz));
}
#define CP_COMMIT() asm volatile("cp.async.commit_group;" ::: "memory")
#define CP_WAIT0()  asm volatile("cp.async.wait_group 0;" ::: "memory")
#define CP_WAIT1()  asm volatile("cp.async.wait_group 1;" ::: "memory")
#define CP_WAIT2()  asm volatile("cp.async.wait_group 2;" ::: "memory")

__device__ __forceinline__ void split2(float v, __nv_bfloat16& hi, __nv_bfloat16& lo) {
    hi = __float2bfloat16(v);
    lo = __float2bfloat16(v - __bfloat162float(hi));
}
__device__ __forceinline__ uint16_t bfu(__nv_bfloat16 h) {
    return __bfloat16_as_ushort(h);
}

// ============ warp-MMA GEMM, K-chunk 32, 4-stage cp.async + wrap addressing ============
// outMode 0: fp32 C (+bias). outMode 1: split bf16 C (hi col c, lo col 256+c).
// outMode 3: fused QKV epilogue (Q/K -> g_Qs/g_Ks per-head split; V -> g_Vt transposed split).
__global__ void __launch_bounds__(256) gemm_mma(
    const __nv_bfloat16* __restrict__ Ag, const __nv_bfloat16* __restrict__ Bg,
    const float* __restrict__ bias, void* __restrict__ Cg,
    int M, int N, int K, int lda, int ldb, int ldc, int awrap, int bwrap, int outMode,
    long sAz2, long sAz1, long sBz2, long sBz1, long sCz2, long sCz1)
{
    extern __shared__ char sm[];
    uint32_t sbase = smem_u32(sm);

    int tid = threadIdx.x, wid = tid >> 5, lane = tid & 31;
    int z = blockIdx.z;
    const __nv_bfloat16* A = Ag + (long)(z >> 1) * sAz2 + (long)(z & 1) * sAz1;
    const __nv_bfloat16* B = Bg + (long)(z >> 1) * sBz2 + (long)(z & 1) * sBz1;
    int row0 = blockIdx.y * 128, col0 = blockIdx.x * 128;
    A += (size_t)row0 * lda;
    B += (size_t)col0 * ldb;
    int esz = (outMode == 1) ? 2 : 4;
    char* Cb = (char*)Cg + ((long)(z >> 1) * sCz2 + (long)(z & 1) * sCz1
                            + (size_t)row0 * ldc + col0) * esz;
    int Mrem = M - row0, Nrem = N - col0;

    int wm = wid & 3, wn = wid >> 2;
    bool wact = (wm * 32 < Mrem) && (wn * 64 < Nrem);

    int ldrow = tid >> 1, half = tid & 1;
    bool aval = ldrow < Mrem, bval = ldrow < Nrem;
    const char* gaBase = reinterpret_cast<const char*>(A + (size_t)ldrow * lda) + half * 32;
    const char* gbBase = reinterpret_cast<const char*>(B + (size_t)ldrow * ldb) + half * 32;
    uint32_t dstOff = ldrow * (AST * 2) + half * 32;

    uint32_t aoff = ((wm * 32 + (lane & 15)) * AST + ((lane >> 4) * 8)) * 2;
    uint32_t boff = ((wn * 64 + (lane & 7) + ((lane >> 4) & 1) * 8) * AST) * 2
                  + ((lane >> 3) & 1) * 16;

    float acc[2][8][4];
    #pragma unroll
    for (int i = 0; i < 2; i++)
        #pragma unroll
        for (int j = 0; j < 8; j++)
            #pragma unroll
            for (int t = 0; t < 4; t++) acc[i][j][t] = 0.f;

    int nchunk = K >> 5;

    #pragma unroll
    for (int p = 0; p < 3; p++) {
        int koff = p * 32;
        int ka = koff >= awrap ? koff - awrap : koff;
        int kb = koff >= bwrap ? koff - bwrap : koff;
        uint32_t dA = sbase + p * 2 * TILEB + dstOff;
        uint32_t dB = dA + TILEB;
        cp16(dA, gaBase + (size_t)ka * 2, aval);
        cp16(dA + 16, gaBase + (size_t)ka * 2 + 16, aval);
        cp16(dB, gbBase + (size_t)kb * 2, bval);
        cp16(dB + 16, gbBase + (size_t)kb * 2 + 16, bval);
        CP_COMMIT();
    }

    for (int i = 0; i < nchunk; i++) {
        if (i + 3 <= nchunk)      { CP_WAIT2(); }
        else if (i + 2 == nchunk) { CP_WAIT1(); }
        else                      { CP_WAIT0(); }
        __syncthreads();

        int st = i & 3;
        uint32_t sA = sbase + st * 2 * TILEB;
        uint32_t sB = sA + TILEB;
        if (wact) {
            #pragma unroll
            for (int kk = 0; kk < 2; kk++) {
                uint32_t a0[4], a1[4], bf[4][4];
                ldm4(a0, sA + aoff + kk * 32);
                ldm4(a1, sA + aoff + 16 * AST * 2 + kk * 32);
                #pragma unroll
                for (int j = 0; j < 4; j++)
                    ldm4(bf[j], sB + boff + j * 16 * AST * 2 + kk * 32);
                #pragma unroll
                for (int j = 0; j < 4; j++) {
                    mma16816(acc[0][2*j],   a0, bf[j][0], bf[j][1]);
                    mma16816(acc[0][2*j+1], a0, bf[j][2], bf[j][3]);
                    mma16816(acc[1][2*j],   a1, bf[j][0], bf[j][1]);
                    mma16816(acc[1][2*j+1], a1, bf[j][2], bf[j][3]);
                }
            }
        }
        if (i + 3 < nchunk) {
            int koff = (i + 3) * 32;
            int ka = koff >= awrap ? koff - awrap : koff;
            int kb = koff >= bwrap ? koff - bwrap : koff;
            int st2 = (i + 3) & 3;
            uint32_t dA = sbase + st2 * 2 * TILEB + dstOff;
            uint32_t dB = dA + TILEB;
            cp16(dA, gaBase + (size_t)ka * 2, aval);
            cp16(dA + 16, gaBase + (size_t)ka * 2 + 16, aval);
            cp16(dB, gbBase + (size_t)kb * 2, bval);
            cp16(dB + 16, gbBase + (size_t)kb * 2 + 16, bval);
            CP_COMMIT();
        }
    }

    if (!wact) return;
    int grp = lane >> 2, qd = lane & 3;

    if (outMode == 0) {
        float* C = (float*)Cb;
        #pragma unroll
        for (int mt = 0; mt < 2; mt++) {
            int r0 = wm * 32 + mt * 16 + grp;
            #pragma unroll
            for (int nt = 0; nt < 8; nt++) {
                int c = wn * 64 + nt * 8 + qd * 2;
                float b0v = 0.f, b1v = 0.f;
                if (bias && c < Nrem)     b0v = bias[col0 + c];
                if (bias && c + 1 < Nrem) b1v = bias[col0 + c + 1];
                if (r0 < Mrem) {
                    if (c < Nrem)     C[(size_t)r0 * ldc + c]     = acc[mt][nt][0] + b0v;
                    if (c + 1 < Nrem) C[(size_t)r0 * ldc + c + 1] = acc[mt][nt][1] + b1v;
                }
                if (r0 + 8 < Mrem) {
                    if (c < Nrem)     C[(size_t)(r0 + 8) * ldc + c]     = acc[mt][nt][2] + b0v;
                    if (c + 1 < Nrem) C[(size_t)(r0 + 8) * ldc + c + 1] = acc[mt][nt][3] + b1v;
                }
            }
        }
    } else if (outMode == 1) {
        __nv_bfloat16* C = (__nv_bfloat16*)Cb;
        #pragma unroll
        for (int mt = 0; mt < 2; mt++) {
            int r0 = wm * 32 + mt * 16 + grp;
            #pragma unroll
            for (int nt = 0; nt < 8; nt++) {
                int c = wn * 64 + nt * 8 + qd * 2;
                #pragma unroll
                for (int e = 0; e < 4; e++) {
                    int rr = r0 + (e >> 1) * 8;
                    int cc = c + (e & 1);
                    if (rr < Mrem && cc < Nrem) {
                        __nv_bfloat16 hi, lo; split2(acc[mt][nt][e], hi, lo);
                        C[(size_t)rr * ldc + cc] = hi;
                        C[(size_t)rr * ldc + 256 + cc] = lo;
                    }
                }
            }
        }
    } else { // outMode 3
        #pragma unroll
        for (int mt = 0; mt < 2; mt++) {
            int r0 = wm * 32 + mt * 16 + grp;
            #pragma unroll
            for (int nt = 0; nt < 8; nt++) {
                int c = wn * 64 + nt * 8 + qd * 2;
                #pragma unroll
                for (int e = 0; e < 4; e++) {
                    int rr = r0 + (e >> 1) * 8;
                    int cc = c + (e & 1);
                    if (rr < Mrem) {
                        int gc = col0 + cc;
                        float val = acc[mt][nt][e] + bias[gc];
                        int gm = row0 + rr;
                        int b = gm / NTOK, t = gm - b * NTOK;
                        int h = (gc >> 7) & 1;
                        int d = gc & 127;
                        __nv_bfloat16 hi, lo; split2(val, hi, lo);
                        if (gc < 512) {
                            size_t base = ((size_t)(b * 2 + h) * NTOK + t) * 256;
                            __nv_bfloat16* dst = (gc < 256) ? g_Qs : g_Ks;
                            dst[base + d] = hi; dst[base + 128 + d] = lo;
                        } else {
                            size_t base = ((size_t)(b * 2 + h) * 128 + d) * 896 + t;
                            g_Vt[base] = hi; g_Vt[base + 448] = lo;
                        }
                    }
                }
            }
        }
    }
}

// ================ conversion / pointwise kernels ================
__device__ __forceinline__ void convW_one(const float* W, __nv_bfloat16* out,
                                          int K, int N, int id, int nOff, int ldout) {
    int k = id / N, n = id % N;
    __nv_bfloat16 hi, lo; split2(W[(size_t)k * N + n], hi, lo);
    size_t base = (size_t)(nOff + n) * ldout;
    out[base + k] = hi; out[base + K + k] = lo;
}

__global__ void convAll_kernel(const float* __restrict__ W1, const float* __restrict__ W2,
                               const float* __restrict__ Wq, const float* __restrict__ Wk,
                               const float* __restrict__ Wv, const float* __restrict__ Wp,
                               const float* __restrict__ bq, const float* __restrict__ bk,
                               const float* __restrict__ bv) {
    int id = blockIdx.x * 256 + threadIdx.x;
    if (id < 196608) { convW_one(W1, g_W1T, 768, 256, id, 0, 1536); return; }
    id -= 196608;
    if (id < 49152)  { convW_one(W2, g_W2T, 192, 256, id, 0, 384); return; }
    id -= 49152;
    if (id < 65536)  { convW_one(Wq, g_WqkvT, 256, 256, id, 0, 512); return; }
    id -= 65536;
    if (id < 65536)  { convW_one(Wk, g_WqkvT, 256, 256, id, 256, 512); return; }
    id -= 65536;
    if (id < 65536)  { convW_one(Wv, g_WqkvT, 256, 256, id, 512, 512); return; }
    id -= 65536;
    if (id < 65536)  { convW_one(Wp, g_WpT, 256, 256, id, 0, 512); return; }
    id -= 65536;
    if (id < 768) {
        float v = (id < 256) ? bq[id] : (id < 512 ? bk[id - 256] : bv[id - 512]);
        g_bqkv[id] = v;
        return;
    }
    id -= 768;
    if (id < BATCH * EMB) g_pool[id] = 0.f;
}

// ---- coalesced patch extraction ----
// blocks [0, 28672): P1, block -> (b, ph, pr): read 3 channel rows of 224 floats,
//   write 14 patches x 48-col contiguous [hi|lo] segments.
// blocks [28672, 57344): P2, block -> (b, ph2, pr2): read the 7 used patches'
//   56 pixels per channel, write 7 patches x 24-col segments.
__global__ void __launch_bounds__(224) extractBoth_kernel(const float* __restrict__ x) {
    __shared__ float px[3][224];
    int tid = threadIdx.x;
    int bid = blockIdx.x;
    if (bid < 28672) {
        int pr = bid & 15;          // 16 pixel rows per patch
        int rem = bid >> 4;
        int ph = rem % 14;
        int b = rem / 14;
        int y = ph * 16 + pr;
        #pragma unroll
        for (int c = 0; c < 3; c++)
            px[c][tid] = x[((size_t)(b * 3 + c) * 224 + y) * 224 + tid];
        __syncthreads();
        #pragma unroll
        for (int it = 0; it < 3; it++) {
            int idx = tid + it * 224;   // 672 = 14 patches * 48 cols
            int pw = idx / 48, j = idx - pw * 48;
            int pc = j / 3, c = j - pc * 3;
            float v = px[c][pw * 16 + pc];
            __nv_bfloat16 hi, lo; split2(v, hi, lo);
            size_t base = (size_t)(b * 196 + ph * 14 + pw) * 1536 + 48 * pr + j;
            g_A1[base] = hi; g_A1[base + 768] = lo;
        }
    } else {
        bid -= 28672;
        int pr = bid & 7;           // 8 pixel rows per patch
        int rem = bid >> 3;
        int ph = rem % 28;
        int b = rem / 28;
        int y = ph * 8 + pr;
        if (tid < 168) {
            int c = tid / 56, w = tid - c * 56;
            int pi = w / 8, pc = w - pi * 8;
            int xc = (4 * pi + 3) * 8 + pc;
            px[c][w] = x[((size_t)(b * 3 + c) * 224 + y) * 224 + xc];
        }
        __syncthreads();
        if (tid < 168) {            // 7 patches * 24 cols
            int pi = tid / 24, j = tid - pi * 24;
            int pc = j / 3, c = j - pc * 3;
            float v = px[c][pi * 8 + pc];
            __nv_bfloat16 hi, lo; split2(v, hi, lo);
            size_t base = (size_t)(b * 196 + 7 * ph + pi) * 384 + 24 * pr + j;
            g_A2[base] = hi; g_A2[base + 192] = lo;
        }
    }
}

// warp-per-token: build z row, store Z, LN via shuffle, split -> Hs (vectorized)
__global__ void buildZ_ln_kernel(const float* __restrict__ cls1, const float* __restrict__ cls2,
                                 const float* __restrict__ gam, const float* __restrict__ bet) {
    int w = threadIdx.x >> 5, lane = threadIdx.x & 31;
    int tg = blockIdx.x * 8 + w;
    if (tg >= M_TOK) return;
    int t = tg % NTOK, b = tg / NTOK;
    const float* src;
    if (t == 0)        src = cls2;
    else if (t < 197)  src = g_E2 + (size_t)(b * NP + (t - 1)) * EMB;
    else if (t == 197) src = cls1;
    else               src = g_E1 + (size_t)(b * NP + (t - 198)) * EMB;
    int e0 = lane * 8;
    float4 v0 = *reinterpret_cast<const float4*>(src + e0);
    float4 v1 = *reinterpret_cast<const float4*>(src + e0 + 4);
    float v[8] = {v0.x, v0.y, v0.z, v0.w, v1.x, v1.y, v1.z, v1.w};
    float* zp = g_Z + (size_t)tg * EMB + e0;
    *reinterpret_cast<float4*>(zp) = v0;
    *reinterpret_cast<float4*>(zp + 4) = v1;
    float s = 0.f;
    #pragma unroll
    for (int j = 0; j < 8; j++) s += v[j];
    #pragma unroll
    for (int o = 16; o; o >>= 1) s += __shfl_xor_sync(0xffffffffu, s, o);
    float m = s * (1.f / EMB);
    float vs = 0.f;
    #pragma unroll
    for (int j = 0; j < 8; j++) { float d = v[j] - m; vs += d * d; }
    #pragma unroll
    for (int o = 16; o; o >>= 1) vs += __shfl_xor_sync(0xffffffffu, vs, o);
    float rstd = rsqrtf(vs * (1.f / EMB) + 1e-5f);
    float4 g0 = *reinterpret_cast<const float4*>(gam + e0);
    float4 g1 = *reinterpret_cast<const float4*>(gam + e0 + 4);
    float4 b0 = *reinterpret_cast<const float4*>(bet + e0);
    float4 b1 = *reinterpret_cast<const float4*>(bet + e0 + 4);
    float gm[8] = {g0.x, g0.y, g0.z, g0.w, g1.x, g1.y, g1.z, g1.w};
    float bt[8] = {b0.x, b0.y, b0.z, b0.w, b1.x, b1.y, b1.z, b1.w};
    uint32_t hw[4], lw[4];
    #pragma unroll
    for (int j = 0; j < 4; j++) {
        float y0 = (v[2*j] - m) * rstd * gm[2*j] + bt[2*j];
        float y1 = (v[2*j+1] - m) * rstd * gm[2*j+1] + bt[2*j+1];
        __nv_bfloat16 h0, l0, h1, l1;
        split2(y0, h0, l0); split2(y1, h1, l1);
        hw[j] = (uint32_t)bfu(h0) | ((uint32_t)bfu(h1) << 16);
        lw[j] = (uint32_t)bfu(l0) | ((uint32_t)bfu(l1) << 16);
    }
    __nv_bfloat16* hp = g_Hs + (size_t)tg * 512 + e0;
    *reinterpret_cast<uint4*>(hp) = make_uint4(hw[0], hw[1], hw[2], hw[3]);
    *reinterpret_cast<uint4*>(hp + 256) = make_uint4(lw[0], lw[1], lw[2], lw[3]);
}

// warp-per-row single-pass softmax (/16) + split write
__global__ void softmax_split_kernel() {
    int gw = blockIdx.x * 8 + (threadIdx.x >> 5);
    int lane = threadIdx.x & 31;
    int zz = gw / NTOK, q = gw - zz * NTOK;
    const float* row = g_S + ((size_t)zz * NTOK + q) * SLD;
    float vals[14];
    float mx = -INFINITY;
    #pragma unroll
    for (int i = 0; i < 14; i++) {
        int t = lane + 32 * i;
        vals[i] = (t < NTOK) ? row[t] : -INFINITY;
        mx = fmaxf(mx, vals[i]);
    }
    #pragma unroll
    for (int o = 16; o; o >>= 1) mx = fmaxf(mx, __shfl_xor_sync(0xffffffffu, mx, o));
    float sum = 0.f;
    #pragma unroll
    for (int i = 0; i < 14; i++) {
        float ev = expf(vals[i] - mx);
        vals[i] = ev;
        sum += ev;
    }
    #pragma unroll
    for (int o = 16; o; o >>= 1) sum += __shfl_xor_sync(0xffffffffu, sum, o);
    float inv = 1.f / (sum * 16.f);
    __nv_bfloat16* prow = g_Ps + ((size_t)zz * NTOK + q) * 896;
    #pragma unroll
    for (int i = 0; i < 14; i++) {
        int t = lane + 32 * i;
        __nv_bfloat16 hi, lo; split2(vals[i] * inv, hi, lo);
        prow[t] = hi; prow[448 + t] = lo;
    }
}

// warp-per-token LN2 + residual + smem pool accumulation
__global__ void lnres_pool_kernel(const float* __restrict__ gam, const float* __restrict__ bet) {
    __shared__ float acc[256];
    int w = threadIdx.x >> 5, lane = threadIdx.x & 31;
    acc[threadIdx.x] = 0.f;
    __syncthreads();
    int b = blockIdx.y;
    int t = blockIdx.x * 8 + w;
    if (t < NTOK) {
        int e0 = lane * 8;
        size_t idx = ((size_t)b * NTOK + t) * EMB + e0;
        float4 p0 = *reinterpret_cast<const float4*>(g_P + idx);
        float4 p1 = *reinterpret_cast<const float4*>(g_P + idx + 4);
        float v[8] = {p0.x, p0.y, p0.z, p0.w, p1.x, p1.y, p1.z, p1.w};
        float s = 0.f;
        #pragma unroll
        for (int j = 0; j < 8; j++) s += v[j];
        #pragma unroll
        for (int o = 16; o; o >>= 1) s += __shfl_xor_sync(0xffffffffu, s, o);
        float m = s * (1.f / EMB);
        float vs = 0.f;
        #pragma unroll
        for (int j = 0; j < 8; j++) { float d = v[j] - m; vs += d * d; }
        #pragma unroll
        for (int o = 16; o; o >>= 1) vs += __shfl_xor_sync(0xffffffffu, vs, o);
        float rstd = rsqrtf(vs * (1.f / EMB) + 1e-5f);
        float4 z0 = *reinterpret_cast<const float4*>(g_Z + idx);
        float4 z1 = *reinterpret_cast<const float4*>(g_Z + idx + 4);
        float zv[8] = {z0.x, z0.y, z0.z, z0.w, z1.x, z1.y, z1.z, z1.w};
        float4 g0 = *reinterpret_cast<const float4*>(gam + e0);
        float4 g1 = *reinterpret_cast<const float4*>(gam + e0 + 4);
        float4 bb0 = *reinterpret_cast<const float4*>(bet + e0);
        float4 bb1 = *reinterpret_cast<const float4*>(bet + e0 + 4);
        float gmv[8] = {g0.x, g0.y, g0.z, g0.w, g1.x, g1.y, g1.z, g1.w};
        float btv[8] = {bb0.x, bb0.y, bb0.z, bb0.w, bb1.x, bb1.y, bb1.z, bb1.w};
        #pragma unroll
        for (int j = 0; j < 8; j++) {
            float o = (v[j] - m) * rstd * gmv[j] + btv[j];
            atomicAdd(&acc[e0 + j], zv[j] + o);
        }
    }
    __syncthreads();
    atomicAdd(&g_pool[b * EMB + threadIdx.x], acc[threadIdx.x]);
}

__device__ __forceinline__ float blockReduceSum(float v, float* sh) {
    int lane = threadIdx.x & 31, w = threadIdx.x >> 5;
    #pragma unroll
    for (int o = 16; o; o >>= 1) v += __shfl_down_sync(0xffffffffu, v, o);
    if (lane == 0) sh[w] = v;
    __syncthreads();
    if (w == 0) {
        v = (lane < 8) ? sh[lane] : 0.f;
        #pragma unroll
        for (int o = 4; o; o >>= 1) v += __shfl_down_sync(0xffffffffu, v, o);
        if (lane == 0) sh[0] = v;
    }
    __syncthreads();
    float r = sh[0];
    __syncthreads();
    return r;
}

__global__ void head_kernel(const float* __restrict__ gam, const float* __restrict__ bet,
                            const float* __restrict__ Wc, const float* __restrict__ bc,
                            float* __restrict__ out) {
    __shared__ float sh[8];
    int bb = blockIdx.x, e = threadIdx.x;
    float pooled = g_pool[bb * EMB + e] * (1.f / NTOK);
    float m = blockReduceSum(pooled, sh) * (1.f / EMB);
    float d = pooled - m;
    float var = blockReduceSum(d * d, sh) * (1.f / EMB);
    float y = d * rsqrtf(var + 1e-5f) * gam[e] + bet[e];
    float p0 = blockReduceSum(y * Wc[e * 2 + 0], sh);
    float p1 = blockReduceSum(y * Wc[e * 2 + 1], sh);
    if (e == 0) {
        float l0 = p0 + bc[0], l1 = p1 + bc[1];
        float mm = fmaxf(l0, l1);
        float lse = mm + logf(expf(l0 - mm) + expf(l1 - mm));
        out[bb * 2 + 0] = l0 - lse;
        out[bb * 2 + 1] = l1 - lse;
    }
}

// ================ launch ================
extern "C" void kernel_launch(void* const* d_in, const int* in_sizes, int n_in,
                              void* d_out, int out_size)
{
    const float* x    = (const float*)d_in[0];
    const float* W1   = (const float*)d_in[1];
    const float* b1   = (const float*)d_in[2];
    const float* cls1 = (const float*)d_in[3];
    const float* W2   = (const float*)d_in[4];
    const float* b2   = (const float*)d_in[5];
    const float* cls2 = (const float*)d_in[6];
    const float* ln1g = (const float*)d_in[7];
    const float* ln1b = (const float*)d_in[8];
    const float* Wq   = (const float*)d_in[9];
    const float* bq   = (const float*)d_in[10];
    const float* Wk   = (const float*)d_in[11];
    const float* bk   = (const float*)d_in[12];
    const float* Wv   = (const float*)d_in[13];
    const float* bv   = (const float*)d_in[14];
    const float* Wp   = (const float*)d_in[15];
    const float* bp   = (const float*)d_in[16];
    const float* ln2g = (const float*)d_in[17];
    const float* ln2b = (const float*)d_in[18];
    const float* lncg = (const float*)d_in[19];
    const float* lncb = (const float*)d_in[20];
    const float* Wc   = (const float*)d_in[21];
    const float* bc   = (const float*)d_in[22];
    float* out = (float*)d_out;

    __nv_bfloat16 *A1, *A2, *W1T, *W2T, *WqkvT, *WpT, *Hs, *Qs, *Ks, *Vt, *Ps, *Os;
    float *bqkv, *S, *P, *E1, *E2;
    cudaGetSymbolAddress((void**)&A1, g_A1);
    cudaGetSymbolAddress((void**)&A2, g_A2);
    cudaGetSymbolAddress((void**)&W1T, g_W1T);
    cudaGetSymbolAddress((void**)&W2T, g_W2T);
    cudaGetSymbolAddress((void**)&WqkvT, g_WqkvT);
    cudaGetSymbolAddress((void**)&WpT, g_WpT);
    cudaGetSymbolAddress((void**)&bqkv, g_bqkv);
    cudaGetSymbolAddress((void**)&Hs, g_Hs);
    cudaGetSymbolAddress((void**)&Qs, g_Qs);
    cudaGetSymbolAddress((void**)&Ks, g_Ks);
    cudaGetSymbolAddress((void**)&Vt, g_Vt);
    cudaGetSymbolAddress((void**)&S, g_S);
    cudaGetSymbolAddress((void**)&Ps, g_Ps);
    cudaGetSymbolAddress((void**)&Os, g_Os);
    cudaGetSymbolAddress((void**)&P, g_P);
    cudaGetSymbolAddress((void**)&E1, g_E1);
    cudaGetSymbolAddress((void**)&E2, g_E2);

    cudaFuncSetAttribute(gemm_mma, cudaFuncAttributeMaxDynamicSharedMemorySize, GSMEM);

    // 1: weight conversions + pool zero
    convAll_kernel<<<(541440 + 255)/256, 256>>>(W1, W2, Wq, Wk, Wv, Wp, bq, bk, bv);
    // 2: coalesced patch extracts (P1 blocks + P2 blocks)
    extractBoth_kernel<<<57344, 224>>>(x);
    // 3,4: patch-embed GEMMs
    gemm_mma<<<dim3(2,196,1), 256, GSMEM>>>(A1, W1T, b1, E1,
        M_PE, 256, 2304, 1536, 1536, 256, 1536, 768, 0, 0,0,0,0,0,0);
    gemm_mma<<<dim3(2,196,1), 256, GSMEM>>>(A2, W2T, b2, E2,
        M_PE, 256, 576, 384, 384, 256, 384, 192, 0, 0,0,0,0,0,0);
    // 5: fused z-assembly + LN + split (warp per token)
    buildZ_ln_kernel<<<M_TOK/8, 256>>>(cls1, cls2, ln1g, ln1b);
    // 6: fused QKV GEMM with Q/K/V split epilogue
    gemm_mma<<<dim3(6,394,1), 256, GSMEM>>>(Hs, WqkvT, bqkv, Qs,
        M_TOK, 768, 768, 512, 512, 768, 512, 256, 3, 0,0,0,0,0,0);
    // 7: S = Q @ K^T
    gemm_mma<<<dim3(4,4,256), 256, GSMEM>>>(Qs, Ks, nullptr, S,
        NTOK, NTOK, 384, 256, 256, SLD, 256, 128, 0,
        2L*NTOK*256, (long)NTOK*256, 2L*NTOK*256, (long)NTOK*256,
        2L*NTOK*SLD, (long)NTOK*SLD);
    // 8: softmax + split (warp per row)
    softmax_split_kernel<<<(256*NTOK)/8, 256>>>();
    // 9: O = P @ V^T -> split bf16 into Os
    gemm_mma<<<dim3(1,4,256), 256, GSMEM>>>(Ps, Vt, nullptr, Os,
        NTOK, 128, 1344, 896, 896, 512, 896, 448, 1,
        2L*NTOK*896, (long)NTOK*896, 2L*128*896, 128L*896,
        (long)NTOK*512, 128L);
    // 10: projection
    gemm_mma<<<dim3(2,394,1), 256, GSMEM>>>(Os, WpT, bp, P,
        M_TOK, 256, 768, 512, 512, 256, 512, 256, 0, 0,0,0,0,0,0);
    // 11,12: LN2+residual+pool, head
    lnres_pool_kernel<<<dim3(50, BATCH), 256>>>(ln2g, ln2b);
    head_kernel<<<BATCH, 256>>>(lncg, lncb, Wc, bc, out);
}